// round 5
// baseline (speedup 1.0000x reference)
#include <cuda_runtime.h>

#define NB 2
#define NS 2048
#define ND 1024
#define NH 16
#define NHD 64
#define BHS (NB * NH * NS * NHD)

// Scratch (allocation-free rule: __device__ globals)
__device__ float g_q[BHS];
__device__ float g_k[BHS];
__device__ float g_v[BHS];
__device__ float g_attn[BHS];

// ---------------------------------------------------------------------------
// Kernel 1: QKV = x @ Wqkv + bqkv, scattered into per-head [b,h,s,d] scratch.
// 128x128 tile, BK=8, 256 threads, 8x8 per thread.
// ---------------------------------------------------------------------------
__global__ __launch_bounds__(256) void qkv_gemm_kernel(
    const float* __restrict__ x, const float* __restrict__ W,
    const float* __restrict__ bias) {
  __shared__ float As[8 * 132];  // transposed A tile, padded
  __shared__ float Bs[8 * 128];

  const int t = threadIdx.x;
  const int m0 = blockIdx.y * 128;
  const int n0 = blockIdx.x * 128;
  const int ty = t >> 4, tx = t & 15;
  const int arow = t >> 1, akq = (t & 1) * 4;
  const int bkr = t >> 5, bnq = (t & 31) * 4;

  float acc[8][8];
#pragma unroll
  for (int i = 0; i < 8; i++)
#pragma unroll
    for (int j = 0; j < 8; j++) acc[i][j] = 0.f;

  const float* gA = x + (m0 + arow) * ND + akq;
  const float* gB = W + bkr * 3072 + n0 + bnq;

  for (int k0 = 0; k0 < ND; k0 += 8) {
    float4 av = *(const float4*)(gA + k0);
    float4 bv = *(const float4*)(gB + k0 * 3072);
    __syncthreads();
    As[(akq + 0) * 132 + arow] = av.x;
    As[(akq + 1) * 132 + arow] = av.y;
    As[(akq + 2) * 132 + arow] = av.z;
    As[(akq + 3) * 132 + arow] = av.w;
    *(float4*)&Bs[bkr * 128 + bnq] = bv;
    __syncthreads();
#pragma unroll
    for (int kk = 0; kk < 8; kk++) {
      float4 a0 = *(float4*)&As[kk * 132 + ty * 8];
      float4 a1 = *(float4*)&As[kk * 132 + ty * 8 + 4];
      float4 b0 = *(float4*)&Bs[kk * 128 + tx * 8];
      float4 b1 = *(float4*)&Bs[kk * 128 + tx * 8 + 4];
      float a[8] = {a0.x, a0.y, a0.z, a0.w, a1.x, a1.y, a1.z, a1.w};
      float b[8] = {b0.x, b0.y, b0.z, b0.w, b1.x, b1.y, b1.z, b1.w};
#pragma unroll
      for (int i = 0; i < 8; i++)
#pragma unroll
        for (int j = 0; j < 8; j++) acc[i][j] = fmaf(a[i], b[j], acc[i][j]);
    }
  }

  // Epilogue: +bias, scatter into q/k/v [b,h,s,d]
#pragma unroll
  for (int i = 0; i < 8; i++) {
    const int m = m0 + ty * 8 + i;
    const int bb = m >> 11, ss = m & 2047;
#pragma unroll
    for (int j = 0; j < 8; j++) {
      const int n = n0 + tx * 8 + j;
      const float val = acc[i][j] + bias[n];
      const int which = n >> 10;
      const int h = (n >> 6) & 15;
      const int dd = n & 63;
      float* dst = (which == 0) ? g_q : (which == 1) ? g_k : g_v;
      dst[((bb * NH + h) * NS + ss) * NHD + dd] = val;
    }
  }
}

// ---------------------------------------------------------------------------
// Kernel 2: causal flash attention, fp32. Br=Bc=64, hd=64.
// 256 threads: ty in [0,16) owns rows ty*4..+3, tx in [0,16) owns cols tx*4..+3.
// Smem: q_s[d][row] (scaled), kv_s = K transposed [d][col] then V [col][d],
//       p_s = P transposed [col][row]. All 64x64 fp32 (48 KB total).
// Row softmax stats reduced via 16-lane shfl_xor (tx-group == 16-lane segment).
// ---------------------------------------------------------------------------
__global__ __launch_bounds__(256) void flash_kernel() {
  __shared__ float q_s[64 * 64];
  __shared__ float kv_s[64 * 64];
  __shared__ float p_s[64 * 64];

  const int bh = blockIdx.y;
  const int qt = blockIdx.x;
  const int q0 = qt * 64;
  const int t = threadIdx.x;
  const int ty = t >> 4, tx = t & 15;

  // Load Q tile, transposed and pre-scaled by 1/sqrt(64)
  const float* qg = g_q + (bh * NS + q0) * NHD;
  for (int l = t; l < 1024; l += 256) {
    const int row = l >> 4, dq = (l & 15) * 4;
    float4 v = *(const float4*)&qg[row * 64 + dq];
    q_s[(dq + 0) * 64 + row] = v.x * 0.125f;
    q_s[(dq + 1) * 64 + row] = v.y * 0.125f;
    q_s[(dq + 2) * 64 + row] = v.z * 0.125f;
    q_s[(dq + 3) * 64 + row] = v.w * 0.125f;
  }

  float m_i[4], l_i[4], o[4][4];
#pragma unroll
  for (int i = 0; i < 4; i++) {
    m_i[i] = -1e30f;
    l_i[i] = 0.f;
#pragma unroll
    for (int j = 0; j < 4; j++) o[i][j] = 0.f;
  }

  for (int jt = 0; jt <= qt; jt++) {
    const int k0 = jt * 64;

    // Barrier: previous iteration's PV reads of kv_s/p_s complete.
    __syncthreads();

    // Load K tile transposed: kv_s[d][col]
    const float* kg = g_k + (bh * NS + k0) * NHD;
    for (int l = t; l < 1024; l += 256) {
      const int row = l >> 4, dq = (l & 15) * 4;
      float4 v = *(const float4*)&kg[row * 64 + dq];
      kv_s[(dq + 0) * 64 + row] = v.x;
      kv_s[(dq + 1) * 64 + row] = v.y;
      kv_s[(dq + 2) * 64 + row] = v.z;
      kv_s[(dq + 3) * 64 + row] = v.w;
    }
    __syncthreads();

    // S = (Q*scale) K^T : 4x4 per-thread register tile
    float s[4][4];
#pragma unroll
    for (int i = 0; i < 4; i++)
#pragma unroll
      for (int j = 0; j < 4; j++) s[i][j] = 0.f;

#pragma unroll 16
    for (int d = 0; d < 64; d++) {
      float4 qf = *(float4*)&q_s[d * 64 + ty * 4];
      float4 kf = *(float4*)&kv_s[d * 64 + tx * 4];
      s[0][0] = fmaf(qf.x, kf.x, s[0][0]);
      s[0][1] = fmaf(qf.x, kf.y, s[0][1]);
      s[0][2] = fmaf(qf.x, kf.z, s[0][2]);
      s[0][3] = fmaf(qf.x, kf.w, s[0][3]);
      s[1][0] = fmaf(qf.y, kf.x, s[1][0]);
      s[1][1] = fmaf(qf.y, kf.y, s[1][1]);
      s[1][2] = fmaf(qf.y, kf.z, s[1][2]);
      s[1][3] = fmaf(qf.y, kf.w, s[1][3]);
      s[2][0] = fmaf(qf.z, kf.x, s[2][0]);
      s[2][1] = fmaf(qf.z, kf.y, s[2][1]);
      s[2][2] = fmaf(qf.z, kf.z, s[2][2]);
      s[2][3] = fmaf(qf.z, kf.w, s[2][3]);
      s[3][0] = fmaf(qf.w, kf.x, s[3][0]);
      s[3][1] = fmaf(qf.w, kf.y, s[3][1]);
      s[3][2] = fmaf(qf.w, kf.z, s[3][2]);
      s[3][3] = fmaf(qf.w, kf.w, s[3][3]);
    }

    // Causal mask on diagonal tile
    if (jt == qt) {
#pragma unroll
      for (int i = 0; i < 4; i++)
#pragma unroll
        for (int j = 0; j < 4; j++)
          if (k0 + tx * 4 + j > q0 + ty * 4 + i) s[i][j] = -1e30f;
    }

    // Online softmax stats per row (deterministic, replicated across tx group)
#pragma unroll
    for (int i = 0; i < 4; i++) {
      float mx = fmaxf(fmaxf(s[i][0], s[i][1]), fmaxf(s[i][2], s[i][3]));
#pragma unroll
      for (int off = 8; off >= 1; off >>= 1)
        mx = fmaxf(mx, __shfl_xor_sync(0xffffffffu, mx, off, 16));
      const float mnew = fmaxf(m_i[i], mx);
      const float alpha = __expf(m_i[i] - mnew);
      m_i[i] = mnew;
      float ps = 0.f;
#pragma unroll
      for (int j = 0; j < 4; j++) {
        s[i][j] = __expf(s[i][j] - mnew);
        ps += s[i][j];
      }
#pragma unroll
      for (int off = 8; off >= 1; off >>= 1)
        ps += __shfl_xor_sync(0xffffffffu, ps, off, 16);
      l_i[i] = l_i[i] * alpha + ps;
#pragma unroll
      for (int j = 0; j < 4; j++) o[i][j] *= alpha;
    }

    // Store P transposed: p_s[col][row]
#pragma unroll
    for (int j = 0; j < 4; j++)
#pragma unroll
      for (int i = 0; i < 4; i++)
        p_s[(tx * 4 + j) * 64 + ty * 4 + i] = s[i][j];
    __syncthreads();  // P visible; all K reads of kv_s done

    // Load V tile direct layout: kv_s[col][d]
    const float* vg = g_v + (bh * NS + k0) * NHD;
    for (int l = t; l < 1024; l += 256) {
      const int row = l >> 4, dq = (l & 15) * 4;
      *(float4*)&kv_s[row * 64 + dq] = *(const float4*)&vg[row * 64 + dq];
    }
    __syncthreads();

    // O += P V
#pragma unroll 16
    for (int c = 0; c < 64; c++) {
      float4 pf = *(float4*)&p_s[c * 64 + ty * 4];
      float4 vf = *(float4*)&kv_s[c * 64 + tx * 4];
      o[0][0] = fmaf(pf.x, vf.x, o[0][0]);
      o[0][1] = fmaf(pf.x, vf.y, o[0][1]);
      o[0][2] = fmaf(pf.x, vf.z, o[0][2]);
      o[0][3] = fmaf(pf.x, vf.w, o[0][3]);
      o[1][0] = fmaf(pf.y, vf.x, o[1][0]);
      o[1][1] = fmaf(pf.y, vf.y, o[1][1]);
      o[1][2] = fmaf(pf.y, vf.z, o[1][2]);
      o[1][3] = fmaf(pf.y, vf.w, o[1][3]);
      o[2][0] = fmaf(pf.z, vf.x, o[2][0]);
      o[2][1] = fmaf(pf.z, vf.y, o[2][1]);
      o[2][2] = fmaf(pf.z, vf.z, o[2][2]);
      o[2][3] = fmaf(pf.z, vf.w, o[2][3]);
      o[3][0] = fmaf(pf.w, vf.x, o[3][0]);
      o[3][1] = fmaf(pf.w, vf.y, o[3][1]);
      o[3][2] = fmaf(pf.w, vf.z, o[3][2]);
      o[3][3] = fmaf(pf.w, vf.w, o[3][3]);
    }
  }

  // Normalize and store to attn scratch [b,h,s,d]
#pragma unroll
  for (int i = 0; i < 4; i++) {
    const float inv = 1.f / l_i[i];
    float4 w = make_float4(o[i][0] * inv, o[i][1] * inv, o[i][2] * inv,
                           o[i][3] * inv);
    *(float4*)&g_attn[(bh * NS + q0 + ty * 4 + i) * NHD + tx * 4] = w;
  }
}

// ---------------------------------------------------------------------------
// Kernel 3: out = attn_flat @ Wo + bo. Same SGEMM; A-load gathers from
// [b,h,s,d] scratch (fused transpose back to [b,s,h*hd]).
// ---------------------------------------------------------------------------
__global__ __launch_bounds__(256) void out_gemm_kernel(
    const float* __restrict__ W, const float* __restrict__ bias,
    float* __restrict__ out) {
  __shared__ float As[8 * 132];
  __shared__ float Bs[8 * 128];

  const int t = threadIdx.x;
  const int m0 = blockIdx.y * 128;
  const int n0 = blockIdx.x * 128;
  const int ty = t >> 4, tx = t & 15;
  const int arow = t >> 1, akq = (t & 1) * 4;
  const int bkr = t >> 5, bnq = (t & 31) * 4;

  float acc[8][8];
#pragma unroll
  for (int i = 0; i < 8; i++)
#pragma unroll
    for (int j = 0; j < 8; j++) acc[i][j] = 0.f;

  const int m = m0 + arow;
  const int bb = m >> 11, ss = m & 2047;
  const int base0 = bb * (NH * NS * NHD) + ss * NHD;
  const float* gB = W + bkr * ND + n0 + bnq;

  for (int k0 = 0; k0 < ND; k0 += 8) {
    const int kk = k0 + akq;
    float4 av =
        *(const float4*)&g_attn[base0 + (kk >> 6) * (NS * NHD) + (kk & 63)];
    float4 bv = *(const float4*)(gB + k0 * ND);
    __syncthreads();
    As[(akq + 0) * 132 + arow] = av.x;
    As[(akq + 1) * 132 + arow] = av.y;
    As[(akq + 2) * 132 + arow] = av.z;
    As[(akq + 3) * 132 + arow] = av.w;
    *(float4*)&Bs[bkr * 128 + bnq] = bv;
    __syncthreads();
#pragma unroll
    for (int kki = 0; kki < 8; kki++) {
      float4 a0 = *(float4*)&As[kki * 132 + ty * 8];
      float4 a1 = *(float4*)&As[kki * 132 + ty * 8 + 4];
      float4 b0 = *(float4*)&Bs[kki * 128 + tx * 8];
      float4 b1 = *(float4*)&Bs[kki * 128 + tx * 8 + 4];
      float a[8] = {a0.x, a0.y, a0.z, a0.w, a1.x, a1.y, a1.z, a1.w};
      float b[8] = {b0.x, b0.y, b0.z, b0.w, b1.x, b1.y, b1.z, b1.w};
#pragma unroll
      for (int i = 0; i < 8; i++)
#pragma unroll
        for (int j = 0; j < 8; j++) acc[i][j] = fmaf(a[i], b[j], acc[i][j]);
    }
  }

#pragma unroll
  for (int i = 0; i < 8; i++) {
    const int mm = m0 + ty * 8 + i;
    float4 o0 = make_float4(acc[i][0] + bias[n0 + tx * 8 + 0],
                            acc[i][1] + bias[n0 + tx * 8 + 1],
                            acc[i][2] + bias[n0 + tx * 8 + 2],
                            acc[i][3] + bias[n0 + tx * 8 + 3]);
    float4 o1 = make_float4(acc[i][4] + bias[n0 + tx * 8 + 4],
                            acc[i][5] + bias[n0 + tx * 8 + 5],
                            acc[i][6] + bias[n0 + tx * 8 + 6],
                            acc[i][7] + bias[n0 + tx * 8 + 7]);
    *(float4*)&out[mm * ND + n0 + tx * 8] = o0;
    *(float4*)&out[mm * ND + n0 + tx * 8 + 4] = o1;
  }
}

// ---------------------------------------------------------------------------
// Launch: x @ Wqkv -> flash attention -> @ Wo. Default stream (capturable).
// Input order per metadata: x, mask(ignored; causal is hardcoded), Wqkv,
// bqkv, Wo, bo.
// ---------------------------------------------------------------------------
extern "C" void kernel_launch(void* const* d_in, const int* in_sizes, int n_in,
                              void* d_out, int out_size) {
  (void)in_sizes;
  (void)n_in;
  (void)out_size;
  const float* x = (const float*)d_in[0];
  const float* Wqkv = (const float*)d_in[2];
  const float* bqkv = (const float*)d_in[3];
  const float* Wo = (const float*)d_in[4];
  const float* bo = (const float*)d_in[5];
  float* out = (float*)d_out;

  qkv_gemm_kernel<<<dim3(3072 / 128, 4096 / 128), 256>>>(x, Wqkv, bqkv);
  flash_kernel<<<dim3(NS / 64, NB * NH), 256>>>();
  out_gemm_kernel<<<dim3(ND / 128, 4096 / 128), 256>>>(Wo, bo, out);
}

// round 8
// speedup vs baseline: 1.3863x; 1.3863x over previous
#include <cuda_runtime.h>
#include <cuda_bf16.h>
#include <cstdint>

#define NB 2
#define NS 2048
#define ND 1024
#define NH 16
#define NHD 64
#define BHS (NB * NH * NS * NHD)

// Scratch (allocation-free rule: __device__ globals)
__device__ float g_q[BHS];
__device__ float g_k[BHS];
__device__ float g_v[BHS];
__device__ float g_attn[BHS];

// ---------------------------------------------------------------------------
// Stage layout (bytes, per double-buffer stage)
//   A_hi [m 0..127][k 0..31] bf16, row stride 40 bf16 (80 B)   : 10240
//   A_lo  same                                                  : 10240
//   B_hi [k 0..31][n 0..127] bf16, row stride 136 bf16 (272 B)  :  8704
//   B_lo  same                                                  :  8704
// ---------------------------------------------------------------------------
#define A_STRIDE_B 80u
#define B_STRIDE_B 272u
#define OFF_A_LO 10240u
#define OFF_B_HI 20480u
#define OFF_B_LO 29184u
#define STAGE_SZ 37888u
#define GEMM_SMEM (2 * 37888)

__device__ __forceinline__ uint32_t smem_u32(const void* p) {
  uint32_t a;
  asm("{ .reg .u64 t; cvta.to.shared.u64 t, %1; cvt.u32.u64 %0, t; }"
      : "=r"(a) : "l"(p));
  return a;
}

__device__ __forceinline__ void ldmx4(uint32_t* r, uint32_t a) {
  asm volatile(
      "ldmatrix.sync.aligned.m8n8.x4.shared.b16 {%0,%1,%2,%3}, [%4];"
      : "=r"(r[0]), "=r"(r[1]), "=r"(r[2]), "=r"(r[3])
      : "r"(a));
}
__device__ __forceinline__ void ldmx4t(uint32_t* r, uint32_t a) {
  asm volatile(
      "ldmatrix.sync.aligned.m8n8.x4.trans.shared.b16 {%0,%1,%2,%3}, [%4];"
      : "=r"(r[0]), "=r"(r[1]), "=r"(r[2]), "=r"(r[3])
      : "r"(a));
}
__device__ __forceinline__ void mma16816(float* c, const uint32_t* a,
                                         const uint32_t* b) {
  asm volatile(
      "mma.sync.aligned.m16n8k16.row.col.f32.bf16.bf16.f32 "
      "{%0,%1,%2,%3}, {%4,%5,%6,%7}, {%8,%9}, {%0,%1,%2,%3};"
      : "+f"(c[0]), "+f"(c[1]), "+f"(c[2]), "+f"(c[3])
      : "r"(a[0]), "r"(a[1]), "r"(a[2]), "r"(a[3]), "r"(b[0]), "r"(b[1]));
}

// Split a pair of floats into packed bf16 hi and bf16 residual words.
__device__ __forceinline__ void cvt_pair(float a, float b, uint32_t& hi,
                                         uint32_t& lo) {
  const uint32_t ah = (uint32_t)__bfloat16_as_ushort(__float2bfloat16_rn(a));
  const uint32_t bh = (uint32_t)__bfloat16_as_ushort(__float2bfloat16_rn(b));
  hi = (bh << 16) | ah;
  const float ar = a - __uint_as_float(ah << 16);
  const float br = b - __uint_as_float(bh << 16);
  const uint32_t al = (uint32_t)__bfloat16_as_ushort(__float2bfloat16_rn(ar));
  const uint32_t bl = (uint32_t)__bfloat16_as_ushort(__float2bfloat16_rn(br));
  lo = (bl << 16) | al;
}

// ---------------------------------------------------------------------------
// Gmem -> register staging for one K-chunk of 32.
// MODE 0: A = x [4096,1024];  MODE 1: A gathered from g_attn [b,h,s,d].
// ---------------------------------------------------------------------------
template <int MODE>
__device__ __forceinline__ void load_regs(float4* av, float4* bv,
                                          const float* __restrict__ A,
                                          const float* __restrict__ W, int m0,
                                          int n0, int k0, int t) {
  const int NW = (MODE == 0) ? 3072 : 1024;
#pragma unroll
  for (int i = 0; i < 4; i++) {
    const int lin = i * 256 + t;
    const int r = lin >> 3, kq = lin & 7;
    const float* src;
    if (MODE == 0) {
      src = A + (m0 + r) * ND + k0 + kq * 4;
    } else {
      const int m = m0 + r;
      const int bb = m >> 11, ss = m & 2047;
      const int k = k0 + kq * 4;
      src = g_attn + bb * (NH * NS * NHD) + (k >> 6) * (NS * NHD) + ss * NHD +
            (k & 63);
    }
    av[i] = *(const float4*)src;
  }
#pragma unroll
  for (int i = 0; i < 4; i++) {
    const int lin = i * 256 + t;
    const int kr = lin >> 5, nq = lin & 31;
    bv[i] = *(const float4*)(W + (k0 + kr) * NW + n0 + nq * 4);
  }
}

__device__ __forceinline__ void store_stage(char* sm, const float4* av,
                                            const float4* bv, int t) {
#pragma unroll
  for (int i = 0; i < 4; i++) {
    const int lin = i * 256 + t;
    const int r = lin >> 3, kq = lin & 7;
    uint32_t h0, l0, h1, l1;
    cvt_pair(av[i].x, av[i].y, h0, l0);
    cvt_pair(av[i].z, av[i].w, h1, l1);
    const uint32_t off = (uint32_t)r * A_STRIDE_B + (uint32_t)kq * 8u;
    *(uint2*)(sm + off) = make_uint2(h0, h1);
    *(uint2*)(sm + OFF_A_LO + off) = make_uint2(l0, l1);
  }
#pragma unroll
  for (int i = 0; i < 4; i++) {
    const int lin = i * 256 + t;
    const int kr = lin >> 5, nq = lin & 31;
    uint32_t h0, l0, h1, l1;
    cvt_pair(bv[i].x, bv[i].y, h0, l0);
    cvt_pair(bv[i].z, bv[i].w, h1, l1);
    const uint32_t off = (uint32_t)kr * B_STRIDE_B + (uint32_t)nq * 8u;
    *(uint2*)(sm + OFF_B_HI + off) = make_uint2(h0, h1);
    *(uint2*)(sm + OFF_B_LO + off) = make_uint2(l0, l1);
  }
}

// One stage of MMA: 2 k16 steps, 4x4 warp tiles, bf16x3 terms.
__device__ __forceinline__ void compute_stage(uint32_t sb, float acc[4][4][4],
                                              int lane, int mtr, int ntr) {
  const uint32_t rsel = (uint32_t)(lane & 15);
  const uint32_t osel = (uint32_t)(lane >> 4);
#pragma unroll
  for (int ks = 0; ks < 2; ks++) {
    const uint32_t kk = (uint32_t)ks * 16u;
    uint32_t ahi[4][4], alo[4][4];
#pragma unroll
    for (int mi = 0; mi < 4; mi++) {
      const uint32_t ad = sb + ((uint32_t)(mtr + mi * 16) + rsel) * A_STRIDE_B +
                          (kk + osel * 8u) * 2u;
      ldmx4(ahi[mi], ad);
      ldmx4(alo[mi], ad + OFF_A_LO);
    }
    uint32_t bhi[4][2], blo[4][2];
#pragma unroll
    for (int np = 0; np < 2; np++) {
      const uint32_t bd = sb + OFF_B_HI + (kk + rsel) * B_STRIDE_B +
                          ((uint32_t)(ntr + np * 16) + osel * 8u) * 2u;
      uint32_t r4[4];
      ldmx4t(r4, bd);
      bhi[np * 2][0] = r4[0];
      bhi[np * 2][1] = r4[1];
      bhi[np * 2 + 1][0] = r4[2];
      bhi[np * 2 + 1][1] = r4[3];
      ldmx4t(r4, bd + (OFF_B_LO - OFF_B_HI));
      blo[np * 2][0] = r4[0];
      blo[np * 2][1] = r4[1];
      blo[np * 2 + 1][0] = r4[2];
      blo[np * 2 + 1][1] = r4[3];
    }
#pragma unroll
    for (int mi = 0; mi < 4; mi++)
#pragma unroll
      for (int ni = 0; ni < 4; ni++) {
        mma16816(acc[mi][ni], ahi[mi], bhi[ni]);
        mma16816(acc[mi][ni], alo[mi], bhi[ni]);
        mma16816(acc[mi][ni], ahi[mi], blo[ni]);
      }
  }
}

// ---------------------------------------------------------------------------
// bf16x3 tensor-core GEMM.
// MODE 0: C[4096,3072] = x @ Wqkv + bqkv -> scatter q/k/v [b,h,s,d]
// MODE 1: C[4096,1024] = attn_flat @ Wo + bo -> d_out
// ---------------------------------------------------------------------------
template <int MODE>
__global__ __launch_bounds__(256) void gemm_mma(const float* __restrict__ A,
                                                const float* __restrict__ W,
                                                const float* __restrict__ bias,
                                                float* __restrict__ out) {
  extern __shared__ char sm[];
  const uint32_t sb = smem_u32(sm);
  const int t = threadIdx.x;
  const int lane = t & 31, wid = t >> 5;
  const int m0 = blockIdx.y * 128, n0 = blockIdx.x * 128;
  const int mtr = (wid >> 2) * 64;  // warp m origin within CTA tile
  const int ntr = (wid & 3) * 32;   // warp n origin within CTA tile

  float acc[4][4][4];
#pragma unroll
  for (int a = 0; a < 4; a++)
#pragma unroll
    for (int b = 0; b < 4; b++)
#pragma unroll
      for (int c = 0; c < 4; c++) acc[a][b][c] = 0.f;

  float4 av[4], bv[4];
  load_regs<MODE>(av, bv, A, W, m0, n0, 0, t);
  store_stage(sm, av, bv, t);
  __syncthreads();

#pragma unroll 2
  for (int c = 0; c < 32; c++) {
    if (c + 1 < 32) load_regs<MODE>(av, bv, A, W, m0, n0, (c + 1) * 32, t);
    compute_stage(sb + (uint32_t)(c & 1) * STAGE_SZ, acc, lane, mtr, ntr);
    if (c + 1 < 32) {
      store_stage(sm + ((c + 1) & 1) * STAGE_SZ, av, bv, t);
      __syncthreads();
    }
  }

  // Epilogue: fragment regs -> gmem. Each float2 is sector-aligned.
#pragma unroll
  for (int mi = 0; mi < 4; mi++) {
#pragma unroll
    for (int ni = 0; ni < 4; ni++) {
      const int r0 = mtr + mi * 16 + (lane >> 2);
      const int cc = ntr + ni * 8 + (lane & 3) * 2;
      const int n = n0 + cc;
      const float b0 = __ldg(&bias[n]);
      const float b1 = __ldg(&bias[n + 1]);
#pragma unroll
      for (int h = 0; h < 2; h++) {
        const int m = m0 + r0 + h * 8;
        const float v0 = acc[mi][ni][h * 2 + 0] + b0;
        const float v1 = acc[mi][ni][h * 2 + 1] + b1;
        if (MODE == 0) {
          const int bb = m >> 11, ss = m & 2047;
          const int which = n >> 10;
          const int hh = (n >> 6) & 15;
          const int dd = n & 63;
          float* dst = (which == 0) ? g_q : (which == 1) ? g_k : g_v;
          *(float2*)&dst[((bb * NH + hh) * NS + ss) * NHD + dd] =
              make_float2(v0, v1);
        } else {
          *(float2*)&out[m * ND + n] = make_float2(v0, v1);
        }
      }
    }
  }
}

// ---------------------------------------------------------------------------
// Kernel 2: causal flash attention, fp32 (unchanged, known-correct).
// ---------------------------------------------------------------------------
__global__ __launch_bounds__(256) void flash_kernel() {
  __shared__ float q_s[64 * 64];
  __shared__ float kv_s[64 * 64];
  __shared__ float p_s[64 * 64];

  const int bh = blockIdx.y;
  const int qt = blockIdx.x;
  const int q0 = qt * 64;
  const int t = threadIdx.x;
  const int ty = t >> 4, tx = t & 15;

  const float* qg = g_q + (bh * NS + q0) * NHD;
  for (int l = t; l < 1024; l += 256) {
    const int row = l >> 4, dq = (l & 15) * 4;
    float4 v = *(const float4*)&qg[row * 64 + dq];
    q_s[(dq + 0) * 64 + row] = v.x * 0.125f;
    q_s[(dq + 1) * 64 + row] = v.y * 0.125f;
    q_s[(dq + 2) * 64 + row] = v.z * 0.125f;
    q_s[(dq + 3) * 64 + row] = v.w * 0.125f;
  }

  float m_i[4], l_i[4], o[4][4];
#pragma unroll
  for (int i = 0; i < 4; i++) {
    m_i[i] = -1e30f;
    l_i[i] = 0.f;
#pragma unroll
    for (int j = 0; j < 4; j++) o[i][j] = 0.f;
  }

  for (int jt = 0; jt <= qt; jt++) {
    const int k0 = jt * 64;
    __syncthreads();

    const float* kg = g_k + (bh * NS + k0) * NHD;
    for (int l = t; l < 1024; l += 256) {
      const int row = l >> 4, dq = (l & 15) * 4;
      float4 v = *(const float4*)&kg[row * 64 + dq];
      kv_s[(dq + 0) * 64 + row] = v.x;
      kv_s[(dq + 1) * 64 + row] = v.y;
      kv_s[(dq + 2) * 64 + row] = v.z;
      kv_s[(dq + 3) * 64 + row] = v.w;
    }
    __syncthreads();

    float s[4][4];
#pragma unroll
    for (int i = 0; i < 4; i++)
#pragma unroll
      for (int j = 0; j < 4; j++) s[i][j] = 0.f;

#pragma unroll 16
    for (int d = 0; d < 64; d++) {
      float4 qf = *(float4*)&q_s[d * 64 + ty * 4];
      float4 kf = *(float4*)&kv_s[d * 64 + tx * 4];
      s[0][0] = fmaf(qf.x, kf.x, s[0][0]);
      s[0][1] = fmaf(qf.x, kf.y, s[0][1]);
      s[0][2] = fmaf(qf.x, kf.z, s[0][2]);
      s[0][3] = fmaf(qf.x, kf.w, s[0][3]);
      s[1][0] = fmaf(qf.y, kf.x, s[1][0]);
      s[1][1] = fmaf(qf.y, kf.y, s[1][1]);
      s[1][2] = fmaf(qf.y, kf.z, s[1][2]);
      s[1][3] = fmaf(qf.y, kf.w, s[1][3]);
      s[2][0] = fmaf(qf.z, kf.x, s[2][0]);
      s[2][1] = fmaf(qf.z, kf.y, s[2][1]);
      s[2][2] = fmaf(qf.z, kf.z, s[2][2]);
      s[2][3] = fmaf(qf.z, kf.w, s[2][3]);
      s[3][0] = fmaf(qf.w, kf.x, s[3][0]);
      s[3][1] = fmaf(qf.w, kf.y, s[3][1]);
      s[3][2] = fmaf(qf.w, kf.z, s[3][2]);
      s[3][3] = fmaf(qf.w, kf.w, s[3][3]);
    }

    if (jt == qt) {
#pragma unroll
      for (int i = 0; i < 4; i++)
#pragma unroll
        for (int j = 0; j < 4; j++)
          if (k0 + tx * 4 + j > q0 + ty * 4 + i) s[i][j] = -1e30f;
    }

#pragma unroll
    for (int i = 0; i < 4; i++) {
      float mx = fmaxf(fmaxf(s[i][0], s[i][1]), fmaxf(s[i][2], s[i][3]));
#pragma unroll
      for (int off = 8; off >= 1; off >>= 1)
        mx = fmaxf(mx, __shfl_xor_sync(0xffffffffu, mx, off, 16));
      const float mnew = fmaxf(m_i[i], mx);
      const float alpha = __expf(m_i[i] - mnew);
      m_i[i] = mnew;
      float ps = 0.f;
#pragma unroll
      for (int j = 0; j < 4; j++) {
        s[i][j] = __expf(s[i][j] - mnew);
        ps += s[i][j];
      }
#pragma unroll
      for (int off = 8; off >= 1; off >>= 1)
        ps += __shfl_xor_sync(0xffffffffu, ps, off, 16);
      l_i[i] = l_i[i] * alpha + ps;
#pragma unroll
      for (int j = 0; j < 4; j++) o[i][j] *= alpha;
    }

#pragma unroll
    for (int j = 0; j < 4; j++)
#pragma unroll
      for (int i = 0; i < 4; i++)
        p_s[(tx * 4 + j) * 64 + ty * 4 + i] = s[i][j];
    __syncthreads();

    const float* vg = g_v + (bh * NS + k0) * NHD;
    for (int l = t; l < 1024; l += 256) {
      const int row = l >> 4, dq = (l & 15) * 4;
      *(float4*)&kv_s[row * 64 + dq] = *(const float4*)&vg[row * 64 + dq];
    }
    __syncthreads();

#pragma unroll 16
    for (int c = 0; c < 64; c++) {
      float4 pf = *(float4*)&p_s[c * 64 + ty * 4];
      float4 vf = *(float4*)&kv_s[c * 64 + tx * 4];
      o[0][0] = fmaf(pf.x, vf.x, o[0][0]);
      o[0][1] = fmaf(pf.x, vf.y, o[0][1]);
      o[0][2] = fmaf(pf.x, vf.z, o[0][2]);
      o[0][3] = fmaf(pf.x, vf.w, o[0][3]);
      o[1][0] = fmaf(pf.y, vf.x, o[1][0]);
      o[1][1] = fmaf(pf.y, vf.y, o[1][1]);
      o[1][2] = fmaf(pf.y, vf.z, o[1][2]);
      o[1][3] = fmaf(pf.y, vf.w, o[1][3]);
      o[2][0] = fmaf(pf.z, vf.x, o[2][0]);
      o[2][1] = fmaf(pf.z, vf.y, o[2][1]);
      o[2][2] = fmaf(pf.z, vf.z, o[2][2]);
      o[2][3] = fmaf(pf.z, vf.w, o[2][3]);
      o[3][0] = fmaf(pf.w, vf.x, o[3][0]);
      o[3][1] = fmaf(pf.w, vf.y, o[3][1]);
      o[3][2] = fmaf(pf.w, vf.z, o[3][2]);
      o[3][3] = fmaf(pf.w, vf.w, o[3][3]);
    }
  }

#pragma unroll
  for (int i = 0; i < 4; i++) {
    const float inv = 1.f / l_i[i];
    float4 w = make_float4(o[i][0] * inv, o[i][1] * inv, o[i][2] * inv,
                           o[i][3] * inv);
    *(float4*)&g_attn[(bh * NS + q0 + ty * 4 + i) * NHD + tx * 4] = w;
  }
}

// ---------------------------------------------------------------------------
// Launch. Inputs: x, mask(ignored; causal hardcoded), Wqkv, bqkv, Wo, bo.
// ---------------------------------------------------------------------------
extern "C" void kernel_launch(void* const* d_in, const int* in_sizes, int n_in,
                              void* d_out, int out_size) {
  (void)in_sizes;
  (void)n_in;
  (void)out_size;
  const float* x = (const float*)d_in[0];
  const float* Wqkv = (const float*)d_in[2];
  const float* bqkv = (const float*)d_in[3];
  const float* Wo = (const float*)d_in[4];
  const float* bo = (const float*)d_in[5];
  float* out = (float*)d_out;

  static bool attr_set = false;
  if (!attr_set) {
    cudaFuncSetAttribute(gemm_mma<0>,
                         cudaFuncAttributeMaxDynamicSharedMemorySize,
                         GEMM_SMEM);
    cudaFuncSetAttribute(gemm_mma<1>,
                         cudaFuncAttributeMaxDynamicSharedMemorySize,
                         GEMM_SMEM);
    attr_set = true;
  }

  gemm_mma<0><<<dim3(3072 / 128, 4096 / 128), 256, GEMM_SMEM>>>(x, Wqkv, bqkv,
                                                                nullptr);
  flash_kernel<<<dim3(NS / 64, NB * NH), 256>>>();
  gemm_mma<1><<<dim3(ND / 128, 4096 / 128), 256, GEMM_SMEM>>>(nullptr, Wo, bo,
                                                              out);
}

// round 10
// speedup vs baseline: 2.3304x; 1.6810x over previous
#include <cuda_runtime.h>
#include <cuda_bf16.h>
#include <cstdint>

#define NB 2
#define NS 2048
#define ND 1024
#define NH 16
#define NHD 64
#define BHS (NB * NH * NS * NHD)

// Scratch (allocation-free rule: __device__ globals)
__device__ float g_q[BHS];
__device__ float g_k[BHS];
__device__ float g_v[BHS];
__device__ float g_attn[BHS];

// ---------------------------------------------------------------------------
// Common mma.sync helpers (validated in R8)
// ---------------------------------------------------------------------------
__device__ __forceinline__ uint32_t smem_u32(const void* p) {
  uint32_t a;
  asm("{ .reg .u64 t; cvta.to.shared.u64 t, %1; cvt.u32.u64 %0, t; }"
      : "=r"(a) : "l"(p));
  return a;
}

__device__ __forceinline__ void ldmx4(uint32_t* r, uint32_t a) {
  asm volatile(
      "ldmatrix.sync.aligned.m8n8.x4.shared.b16 {%0,%1,%2,%3}, [%4];"
      : "=r"(r[0]), "=r"(r[1]), "=r"(r[2]), "=r"(r[3])
      : "r"(a));
}
__device__ __forceinline__ void ldmx4t(uint32_t* r, uint32_t a) {
  asm volatile(
      "ldmatrix.sync.aligned.m8n8.x4.trans.shared.b16 {%0,%1,%2,%3}, [%4];"
      : "=r"(r[0]), "=r"(r[1]), "=r"(r[2]), "=r"(r[3])
      : "r"(a));
}
__device__ __forceinline__ void mma16816(float* c, const uint32_t* a,
                                         const uint32_t* b) {
  asm volatile(
      "mma.sync.aligned.m16n8k16.row.col.f32.bf16.bf16.f32 "
      "{%0,%1,%2,%3}, {%4,%5,%6,%7}, {%8,%9}, {%0,%1,%2,%3};"
      : "+f"(c[0]), "+f"(c[1]), "+f"(c[2]), "+f"(c[3])
      : "r"(a[0]), "r"(a[1]), "r"(a[2]), "r"(a[3]), "r"(b[0]), "r"(b[1]));
}

// Split a pair of floats into packed bf16 hi and bf16 residual words.
__device__ __forceinline__ void cvt_pair(float a, float b, uint32_t& hi,
                                         uint32_t& lo) {
  const uint32_t ah = (uint32_t)__bfloat16_as_ushort(__float2bfloat16_rn(a));
  const uint32_t bh = (uint32_t)__bfloat16_as_ushort(__float2bfloat16_rn(b));
  hi = (bh << 16) | ah;
  const float ar = a - __uint_as_float(ah << 16);
  const float br = b - __uint_as_float(bh << 16);
  const uint32_t al = (uint32_t)__bfloat16_as_ushort(__float2bfloat16_rn(ar));
  const uint32_t bl = (uint32_t)__bfloat16_as_ushort(__float2bfloat16_rn(br));
  lo = (bl << 16) | al;
}

// ---------------------------------------------------------------------------
// bf16x3 tensor-core GEMM (unchanged from R8, passing).
// ---------------------------------------------------------------------------
#define A_STRIDE_B 80u
#define B_STRIDE_B 272u
#define OFF_A_LO 10240u
#define OFF_B_HI 20480u
#define OFF_B_LO 29184u
#define STAGE_SZ 37888u
#define GEMM_SMEM (2 * 37888)

template <int MODE>
__device__ __forceinline__ void load_regs(float4* av, float4* bv,
                                          const float* __restrict__ A,
                                          const float* __restrict__ W, int m0,
                                          int n0, int k0, int t) {
  const int NW = (MODE == 0) ? 3072 : 1024;
#pragma unroll
  for (int i = 0; i < 4; i++) {
    const int lin = i * 256 + t;
    const int r = lin >> 3, kq = lin & 7;
    const float* src;
    if (MODE == 0) {
      src = A + (m0 + r) * ND + k0 + kq * 4;
    } else {
      const int m = m0 + r;
      const int bb = m >> 11, ss = m & 2047;
      const int k = k0 + kq * 4;
      src = g_attn + bb * (NH * NS * NHD) + (k >> 6) * (NS * NHD) + ss * NHD +
            (k & 63);
    }
    av[i] = *(const float4*)src;
  }
#pragma unroll
  for (int i = 0; i < 4; i++) {
    const int lin = i * 256 + t;
    const int kr = lin >> 5, nq = lin & 31;
    bv[i] = *(const float4*)(W + (k0 + kr) * NW + n0 + nq * 4);
  }
}

__device__ __forceinline__ void store_stage(char* sm, const float4* av,
                                            const float4* bv, int t) {
#pragma unroll
  for (int i = 0; i < 4; i++) {
    const int lin = i * 256 + t;
    const int r = lin >> 3, kq = lin & 7;
    uint32_t h0, l0, h1, l1;
    cvt_pair(av[i].x, av[i].y, h0, l0);
    cvt_pair(av[i].z, av[i].w, h1, l1);
    const uint32_t off = (uint32_t)r * A_STRIDE_B + (uint32_t)kq * 8u;
    *(uint2*)(sm + off) = make_uint2(h0, h1);
    *(uint2*)(sm + OFF_A_LO + off) = make_uint2(l0, l1);
  }
#pragma unroll
  for (int i = 0; i < 4; i++) {
    const int lin = i * 256 + t;
    const int kr = lin >> 5, nq = lin & 31;
    uint32_t h0, l0, h1, l1;
    cvt_pair(bv[i].x, bv[i].y, h0, l0);
    cvt_pair(bv[i].z, bv[i].w, h1, l1);
    const uint32_t off = (uint32_t)kr * B_STRIDE_B + (uint32_t)nq * 8u;
    *(uint2*)(sm + OFF_B_HI + off) = make_uint2(h0, h1);
    *(uint2*)(sm + OFF_B_LO + off) = make_uint2(l0, l1);
  }
}

__device__ __forceinline__ void compute_stage(uint32_t sb, float acc[4][4][4],
                                              int lane, int mtr, int ntr) {
  const uint32_t rsel = (uint32_t)(lane & 15);
  const uint32_t osel = (uint32_t)(lane >> 4);
#pragma unroll
  for (int ks = 0; ks < 2; ks++) {
    const uint32_t kk = (uint32_t)ks * 16u;
    uint32_t ahi[4][4], alo[4][4];
#pragma unroll
    for (int mi = 0; mi < 4; mi++) {
      const uint32_t ad = sb + ((uint32_t)(mtr + mi * 16) + rsel) * A_STRIDE_B +
                          (kk + osel * 8u) * 2u;
      ldmx4(ahi[mi], ad);
      ldmx4(alo[mi], ad + OFF_A_LO);
    }
    uint32_t bhi[4][2], blo[4][2];
#pragma unroll
    for (int np = 0; np < 2; np++) {
      const uint32_t bd = sb + OFF_B_HI + (kk + rsel) * B_STRIDE_B +
                          ((uint32_t)(ntr + np * 16) + osel * 8u) * 2u;
      uint32_t r4[4];
      ldmx4t(r4, bd);
      bhi[np * 2][0] = r4[0];
      bhi[np * 2][1] = r4[1];
      bhi[np * 2 + 1][0] = r4[2];
      bhi[np * 2 + 1][1] = r4[3];
      ldmx4t(r4, bd + (OFF_B_LO - OFF_B_HI));
      blo[np * 2][0] = r4[0];
      blo[np * 2][1] = r4[1];
      blo[np * 2 + 1][0] = r4[2];
      blo[np * 2 + 1][1] = r4[3];
    }
#pragma unroll
    for (int mi = 0; mi < 4; mi++)
#pragma unroll
      for (int ni = 0; ni < 4; ni++) {
        mma16816(acc[mi][ni], ahi[mi], bhi[ni]);
        mma16816(acc[mi][ni], alo[mi], bhi[ni]);
        mma16816(acc[mi][ni], ahi[mi], blo[ni]);
      }
  }
}

template <int MODE>
__global__ __launch_bounds__(256) void gemm_mma(const float* __restrict__ A,
                                                const float* __restrict__ W,
                                                const float* __restrict__ bias,
                                                float* __restrict__ out) {
  extern __shared__ char sm[];
  const uint32_t sb = smem_u32(sm);
  const int t = threadIdx.x;
  const int lane = t & 31, wid = t >> 5;
  const int m0 = blockIdx.y * 128, n0 = blockIdx.x * 128;
  const int mtr = (wid >> 2) * 64;
  const int ntr = (wid & 3) * 32;

  float acc[4][4][4];
#pragma unroll
  for (int a = 0; a < 4; a++)
#pragma unroll
    for (int b = 0; b < 4; b++)
#pragma unroll
      for (int c = 0; c < 4; c++) acc[a][b][c] = 0.f;

  float4 av[4], bv[4];
  load_regs<MODE>(av, bv, A, W, m0, n0, 0, t);
  store_stage(sm, av, bv, t);
  __syncthreads();

#pragma unroll 2
  for (int c = 0; c < 32; c++) {
    if (c + 1 < 32) load_regs<MODE>(av, bv, A, W, m0, n0, (c + 1) * 32, t);
    compute_stage(sb + (uint32_t)(c & 1) * STAGE_SZ, acc, lane, mtr, ntr);
    if (c + 1 < 32) {
      store_stage(sm + ((c + 1) & 1) * STAGE_SZ, av, bv, t);
      __syncthreads();
    }
  }

#pragma unroll
  for (int mi = 0; mi < 4; mi++) {
#pragma unroll
    for (int ni = 0; ni < 4; ni++) {
      const int r0 = mtr + mi * 16 + (lane >> 2);
      const int cc = ntr + ni * 8 + (lane & 3) * 2;
      const int n = n0 + cc;
      const float b0 = __ldg(&bias[n]);
      const float b1 = __ldg(&bias[n + 1]);
#pragma unroll
      for (int h = 0; h < 2; h++) {
        const int m = m0 + r0 + h * 8;
        const float v0 = acc[mi][ni][h * 2 + 0] + b0;
        const float v1 = acc[mi][ni][h * 2 + 1] + b1;
        if (MODE == 0) {
          const int bb = m >> 11, ss = m & 2047;
          const int which = n >> 10;
          const int hh = (n >> 6) & 15;
          const int dd = n & 63;
          float* dst = (which == 0) ? g_q : (which == 1) ? g_k : g_v;
          *(float2*)&dst[((bb * NH + hh) * NS + ss) * NHD + dd] =
              make_float2(v0, v1);
        } else {
          *(float2*)&out[m * ND + n] = make_float2(v0, v1);
        }
      }
    }
  }
}

// ---------------------------------------------------------------------------
// Kernel 2: causal flash attention on tensor cores (bf16x3 mma.sync).
// Br=128 (8 warps x 16 q rows), Bc=64, hd=64.
// Q frags held in registers across the whole KV loop. P stays in registers
// (S C-fragments repack directly into PV A-fragments). Row stride 144 B for
// all smem tiles -> conflict-free ldmatrix phases.
// ---------------------------------------------------------------------------
#define FSTR 144u
#define FLO 9216u  // lo-plane offset inside a 18432-B buffer

__global__ __launch_bounds__(256) void flash_mma() {
  __shared__ __align__(16) char bufA[18432];  // Q-hi staging, then V hi/lo
  __shared__ __align__(16) char bufB[18432];  // Q-lo staging, then K hi/lo

  const int bh = blockIdx.y;
  const int q0 = blockIdx.x * 128;
  const int t = threadIdx.x, lane = t & 31, wid = t >> 5;
  const uint32_t sbA = smem_u32(bufA), sbB = smem_u32(bufB);
  const uint32_t rsel = (uint32_t)(lane & 15), osel = (uint32_t)(lane >> 4);

  // Stage Q (pre-scaled by 1/sqrt(64)), hi->bufA, lo->bufB
  {
    const float* qg = g_q + (bh * NS + q0) * NHD;
#pragma unroll
    for (int i = 0; i < 8; i++) {
      const int lin = i * 256 + t;
      const int row = lin >> 4, c4 = lin & 15;
      const float4 v = *(const float4*)&qg[row * 64 + c4 * 4];
      uint32_t h0, l0, h1, l1;
      cvt_pair(v.x * 0.125f, v.y * 0.125f, h0, l0);
      cvt_pair(v.z * 0.125f, v.w * 0.125f, h1, l1);
      *(uint2*)(bufA + row * FSTR + c4 * 8) = make_uint2(h0, h1);
      *(uint2*)(bufB + row * FSTR + c4 * 8) = make_uint2(l0, l1);
    }
  }
  __syncthreads();

  // Q fragments: 4 k16 steps, hi + lo
  uint32_t qh[4][4], ql[4][4];
#pragma unroll
  for (int ks = 0; ks < 4; ks++) {
    const uint32_t off =
        (uint32_t)(wid * 16) * FSTR + rsel * FSTR + ((uint32_t)ks * 16 + osel * 8) * 2;
    ldmx4(qh[ks], sbA + off);
    ldmx4(ql[ks], sbB + off);
  }
  __syncthreads();

  float oc[8][4];
#pragma unroll
  for (int i = 0; i < 8; i++)
#pragma unroll
    for (int j = 0; j < 4; j++) oc[i][j] = 0.f;
  float m2[2] = {-1e30f, -1e30f}, l2[2] = {0.f, 0.f};

  const int jmax = (q0 + 128) / 64;
  for (int jt = 0; jt < jmax; jt++) {
    const int k0 = jt * 64;
    // Load K -> bufB, V -> bufA (hi/lo planes)
    {
      const float* kg = g_k + (bh * NS + k0) * NHD;
      const float* vg = g_v + (bh * NS + k0) * NHD;
#pragma unroll
      for (int i = 0; i < 4; i++) {
        const int lin = i * 256 + t;
        const int row = lin >> 4, c4 = lin & 15;
        const float4 kv = *(const float4*)&kg[row * 64 + c4 * 4];
        const float4 vv = *(const float4*)&vg[row * 64 + c4 * 4];
        uint32_t h0, l0, h1, l1;
        cvt_pair(kv.x, kv.y, h0, l0);
        cvt_pair(kv.z, kv.w, h1, l1);
        *(uint2*)(bufB + row * FSTR + c4 * 8) = make_uint2(h0, h1);
        *(uint2*)(bufB + FLO + row * FSTR + c4 * 8) = make_uint2(l0, l1);
        cvt_pair(vv.x, vv.y, h0, l0);
        cvt_pair(vv.z, vv.w, h1, l1);
        *(uint2*)(bufA + row * FSTR + c4 * 8) = make_uint2(h0, h1);
        *(uint2*)(bufA + FLO + row * FSTR + c4 * 8) = make_uint2(l0, l1);
      }
    }
    __syncthreads();

    // S = Q K^T (bf16x3). K is [key][d] = [n][k] row-major -> non-trans
    // ldmatrix.x4 yields B fragments for two adjacent n8 tiles.
    float sf[8][4];
#pragma unroll
    for (int i = 0; i < 8; i++)
#pragma unroll
      for (int j = 0; j < 4; j++) sf[i][j] = 0.f;

#pragma unroll
    for (int ks = 0; ks < 4; ks++) {
#pragma unroll
      for (int p = 0; p < 4; p++) {
        const uint32_t addr =
            sbB +
            ((uint32_t)(p * 16) + (uint32_t)(lane & 7) + (uint32_t)(lane >> 4) * 8) *
                FSTR +
            ((uint32_t)ks * 16 + (uint32_t)((lane >> 3) & 1) * 8) * 2;
        uint32_t kh[4], kl[4];
        ldmx4(kh, addr);
        ldmx4(kl, addr + FLO);
        mma16816(sf[2 * p], qh[ks], kh);
        mma16816(sf[2 * p], ql[ks], kh);
        mma16816(sf[2 * p], qh[ks], kl);
        mma16816(sf[2 * p + 1], qh[ks], kh + 2);
        mma16816(sf[2 * p + 1], ql[ks], kh + 2);
        mma16816(sf[2 * p + 1], qh[ks], kl + 2);
      }
    }

    // Causal mask (only tiles in the diagonal band of this warp)
    const int r0g = q0 + wid * 16 + (lane >> 2);
    if (k0 + 63 > q0 + wid * 16) {
#pragma unroll
      for (int nt = 0; nt < 8; nt++) {
        const int c = k0 + nt * 8 + (lane & 3) * 2;
        if (c > r0g) sf[nt][0] = -1e30f;
        if (c + 1 > r0g) sf[nt][1] = -1e30f;
        if (c > r0g + 8) sf[nt][2] = -1e30f;
        if (c + 1 > r0g + 8) sf[nt][3] = -1e30f;
      }
    }

    // Online softmax: each thread owns 2 rows; quad (xor 1,2) holds the row.
#pragma unroll
    for (int h = 0; h < 2; h++) {
      float mx = -1e30f;
#pragma unroll
      for (int nt = 0; nt < 8; nt++)
        mx = fmaxf(mx, fmaxf(sf[nt][2 * h], sf[nt][2 * h + 1]));
      mx = fmaxf(mx, __shfl_xor_sync(0xffffffffu, mx, 1));
      mx = fmaxf(mx, __shfl_xor_sync(0xffffffffu, mx, 2));
      const float mnew = fmaxf(m2[h], mx);
      const float alpha = __expf(m2[h] - mnew);
      m2[h] = mnew;
      float ps = 0.f;
#pragma unroll
      for (int nt = 0; nt < 8; nt++) {
        sf[nt][2 * h] = __expf(sf[nt][2 * h] - mnew);
        sf[nt][2 * h + 1] = __expf(sf[nt][2 * h + 1] - mnew);
        ps += sf[nt][2 * h] + sf[nt][2 * h + 1];
      }
      ps += __shfl_xor_sync(0xffffffffu, ps, 1);
      ps += __shfl_xor_sync(0xffffffffu, ps, 2);
      l2[h] = l2[h] * alpha + ps;
#pragma unroll
      for (int dt = 0; dt < 8; dt++) {
        oc[dt][2 * h] *= alpha;
        oc[dt][2 * h + 1] *= alpha;
      }
    }

    // Pack P into PV A-fragments (2 S n-tiles -> one k16 A fragment)
    uint32_t ph[4][4], pl[4][4];
#pragma unroll
    for (int kk = 0; kk < 4; kk++) {
      cvt_pair(sf[2 * kk][0], sf[2 * kk][1], ph[kk][0], pl[kk][0]);
      cvt_pair(sf[2 * kk][2], sf[2 * kk][3], ph[kk][1], pl[kk][1]);
      cvt_pair(sf[2 * kk + 1][0], sf[2 * kk + 1][1], ph[kk][2], pl[kk][2]);
      cvt_pair(sf[2 * kk + 1][2], sf[2 * kk + 1][3], ph[kk][3], pl[kk][3]);
    }

    // O += P V (bf16x3). V is [key][d] = [k][n] row-major -> trans ldmatrix.
#pragma unroll
    for (int kk = 0; kk < 4; kk++) {
#pragma unroll
      for (int dp = 0; dp < 4; dp++) {
        const uint32_t addr = sbA + ((uint32_t)kk * 16 + rsel) * FSTR +
                              ((uint32_t)(dp * 16) + osel * 8) * 2;
        uint32_t vh[4], vl[4];
        ldmx4t(vh, addr);
        ldmx4t(vl, addr + FLO);
        mma16816(oc[2 * dp], ph[kk], vh);
        mma16816(oc[2 * dp], pl[kk], vh);
        mma16816(oc[2 * dp], ph[kk], vl);
        mma16816(oc[2 * dp + 1], ph[kk], vh + 2);
        mma16816(oc[2 * dp + 1], pl[kk], vh + 2);
        mma16816(oc[2 * dp + 1], ph[kk], vl + 2);
      }
    }
    __syncthreads();
  }

  // Normalize and write O to g_attn [b,h,s,d]
  const int r0g = q0 + wid * 16 + (lane >> 2);
#pragma unroll
  for (int h = 0; h < 2; h++) {
    const float inv = 1.f / l2[h];
    float* og = g_attn + (bh * NS + r0g + h * 8) * NHD + (lane & 3) * 2;
#pragma unroll
    for (int dt = 0; dt < 8; dt++)
      *(float2*)&og[dt * 8] =
          make_float2(oc[dt][2 * h] * inv, oc[dt][2 * h + 1] * inv);
  }
}

// ---------------------------------------------------------------------------
// Launch. Inputs: x, mask(ignored; causal hardcoded), Wqkv, bqkv, Wo, bo.
// ---------------------------------------------------------------------------
extern "C" void kernel_launch(void* const* d_in, const int* in_sizes, int n_in,
                              void* d_out, int out_size) {
  (void)in_sizes;
  (void)n_in;
  (void)out_size;
  const float* x = (const float*)d_in[0];
  const float* Wqkv = (const float*)d_in[2];
  const float* bqkv = (const float*)d_in[3];
  const float* Wo = (const float*)d_in[4];
  const float* bo = (const float*)d_in[5];
  float* out = (float*)d_out;

  static bool attr_set = false;
  if (!attr_set) {
    cudaFuncSetAttribute(gemm_mma<0>,
                         cudaFuncAttributeMaxDynamicSharedMemorySize,
                         GEMM_SMEM);
    cudaFuncSetAttribute(gemm_mma<1>,
                         cudaFuncAttributeMaxDynamicSharedMemorySize,
                         GEMM_SMEM);
    attr_set = true;
  }

  gemm_mma<0><<<dim3(3072 / 128, 4096 / 128), 256, GEMM_SMEM>>>(x, Wqkv, bqkv,
                                                                nullptr);
  flash_mma<<<dim3(NS / 128, NB * NH), 256>>>();
  gemm_mma<1><<<dim3(ND / 128, 4096 / 128), 256, GEMM_SMEM>>>(nullptr, Wo, bo,
                                                              out);
}

// round 11
// speedup vs baseline: 2.7043x; 1.1604x over previous
#include <cuda_runtime.h>
#include <cuda_bf16.h>
#include <cstdint>

#define NB 2
#define NS 2048
#define ND 1024
#define NH 16
#define NHD 64
#define BHS (NB * NH * NS * NHD)

// Persistent bf16 hi/lo planes (allocation-free rule: __device__ globals)
__device__ unsigned short g_x_hi[4096 * ND], g_x_lo[4096 * ND];
__device__ unsigned short g_wqkv_hi[ND * 3072], g_wqkv_lo[ND * 3072];
__device__ unsigned short g_wo_hi[ND * ND], g_wo_lo[ND * ND];
__device__ unsigned short g_q_hi[BHS], g_q_lo[BHS];
__device__ unsigned short g_k_hi[BHS], g_k_lo[BHS];
__device__ unsigned short g_v_hi[BHS], g_v_lo[BHS];
__device__ unsigned short g_attn_hi[BHS], g_attn_lo[BHS];

// ---------------------------------------------------------------------------
// Helpers
// ---------------------------------------------------------------------------
__device__ __forceinline__ uint32_t smem_u32(const void* p) {
  uint32_t a;
  asm("{ .reg .u64 t; cvta.to.shared.u64 t, %1; cvt.u32.u64 %0, t; }"
      : "=r"(a) : "l"(p));
  return a;
}
__device__ __forceinline__ void ldmx4(uint32_t* r, uint32_t a) {
  asm volatile(
      "ldmatrix.sync.aligned.m8n8.x4.shared.b16 {%0,%1,%2,%3}, [%4];"
      : "=r"(r[0]), "=r"(r[1]), "=r"(r[2]), "=r"(r[3])
      : "r"(a));
}
__device__ __forceinline__ void ldmx4t(uint32_t* r, uint32_t a) {
  asm volatile(
      "ldmatrix.sync.aligned.m8n8.x4.trans.shared.b16 {%0,%1,%2,%3}, [%4];"
      : "=r"(r[0]), "=r"(r[1]), "=r"(r[2]), "=r"(r[3])
      : "r"(a));
}
__device__ __forceinline__ void mma16816(float* c, const uint32_t* a,
                                         const uint32_t* b) {
  asm volatile(
      "mma.sync.aligned.m16n8k16.row.col.f32.bf16.bf16.f32 "
      "{%0,%1,%2,%3}, {%4,%5,%6,%7}, {%8,%9}, {%0,%1,%2,%3};"
      : "+f"(c[0]), "+f"(c[1]), "+f"(c[2]), "+f"(c[3])
      : "r"(a[0]), "r"(a[1]), "r"(a[2]), "r"(a[3]), "r"(b[0]), "r"(b[1]));
}
__device__ __forceinline__ void cvt_pair(float a, float b, uint32_t& hi,
                                         uint32_t& lo) {
  const uint32_t ah = (uint32_t)__bfloat16_as_ushort(__float2bfloat16_rn(a));
  const uint32_t bh = (uint32_t)__bfloat16_as_ushort(__float2bfloat16_rn(b));
  hi = (bh << 16) | ah;
  const float ar = a - __uint_as_float(ah << 16);
  const float br = b - __uint_as_float(bh << 16);
  const uint32_t al = (uint32_t)__bfloat16_as_ushort(__float2bfloat16_rn(ar));
  const uint32_t bl = (uint32_t)__bfloat16_as_ushort(__float2bfloat16_rn(br));
  lo = (bl << 16) | al;
}
__device__ __forceinline__ void cpa16(uint32_t dst, const void* src) {
  asm volatile("cp.async.cg.shared.global [%0], [%1], 16;" ::"r"(dst),
               "l"(src));
}
__device__ __forceinline__ void cpa_commit() {
  asm volatile("cp.async.commit_group;");
}
#define CP_WAIT(N) asm volatile("cp.async.wait_group " #N ";")

// ---------------------------------------------------------------------------
// fp32 -> bf16 hi/lo plane converter
// ---------------------------------------------------------------------------
__global__ void cvt_planes(const float* __restrict__ src,
                           unsigned short* __restrict__ hi,
                           unsigned short* __restrict__ lo) {
  const int i = blockIdx.x * blockDim.x + threadIdx.x;
  const float4 v = ((const float4*)src)[i];
  uint32_t h0, l0, h1, l1;
  cvt_pair(v.x, v.y, h0, l0);
  cvt_pair(v.z, v.w, h1, l1);
  ((uint2*)hi)[i] = make_uint2(h0, h1);
  ((uint2*)lo)[i] = make_uint2(l0, l1);
}

// ---------------------------------------------------------------------------
// bf16x3 tensor-core GEMM, cp.async 3-stage pipeline, pre-split operands.
// MODE 0: C[4096,3072] = x @ Wqkv + bqkv -> split into q/k/v hi/lo planes
// MODE 1: C[4096,1024] = attn @ Wo + bo -> d_out (fp32)
// Stage: A_hi(10240) A_lo(10240) B_hi(8704) B_lo(8704) = 37888 B
// ---------------------------------------------------------------------------
#define A_STRIDE_B 80u
#define OFF_A_LO 10240u
#define OFF_B 20480u
#define B_STRIDE_B 272u
#define OFF_B_LO 8704u
#define STAGE_SZ 37888u
#define GEMM_SMEM (3 * 37888)

template <int MODE>
__device__ __forceinline__ void g_load_stage(uint32_t st, int m0, int n0,
                                             int k0, int t) {
  const int NW = (MODE == 0) ? 3072 : 1024;
  const unsigned short* ap[2];
  const unsigned short* wp[2];
  if (MODE == 0) {
    ap[0] = g_x_hi; ap[1] = g_x_lo;
    wp[0] = g_wqkv_hi; wp[1] = g_wqkv_lo;
  } else {
    ap[0] = g_attn_hi; ap[1] = g_attn_lo;
    wp[0] = g_wo_hi; wp[1] = g_wo_lo;
  }
#pragma unroll
  for (int i = 0; i < 4; i++) {
    const int idx = i * 256 + t;
    const int plane = idx >> 9, id = idx & 511;
    const int r = id >> 2, q = id & 3;
    const unsigned short* src;
    if (MODE == 0) {
      src = ap[plane] + (m0 + r) * ND + k0 + q * 8;
    } else {
      const int m = m0 + r;
      const int bb = m >> 11, ss = m & 2047;
      const int k = k0 + q * 8;
      src = ap[plane] + bb * (NH * NS * NHD) + (k >> 6) * (NS * NHD) +
            ss * NHD + (k & 63);
    }
    cpa16(st + (uint32_t)plane * OFF_A_LO + (uint32_t)r * A_STRIDE_B +
              (uint32_t)q * 16u,
          src);
  }
#pragma unroll
  for (int i = 0; i < 4; i++) {
    const int idx = i * 256 + t;
    const int plane = idx >> 9, id = idx & 511;
    const int kr = id >> 4, nq = id & 15;
    cpa16(st + OFF_B + (uint32_t)plane * OFF_B_LO + (uint32_t)kr * B_STRIDE_B +
              (uint32_t)nq * 16u,
          wp[plane] + (k0 + kr) * NW + n0 + nq * 8);
  }
}

__device__ __forceinline__ void g_compute_stage(uint32_t st, float acc[4][4][4],
                                                int lane, int mtr, int ntr) {
  const uint32_t rsel = (uint32_t)(lane & 15);
  const uint32_t osel = (uint32_t)(lane >> 4);
#pragma unroll
  for (int ks = 0; ks < 2; ks++) {
    const uint32_t kk = (uint32_t)ks * 16u;
    uint32_t ahi[4][4], alo[4][4];
#pragma unroll
    for (int mi = 0; mi < 4; mi++) {
      const uint32_t ad = st + ((uint32_t)(mtr + mi * 16) + rsel) * A_STRIDE_B +
                          (kk + osel * 8u) * 2u;
      ldmx4(ahi[mi], ad);
      ldmx4(alo[mi], ad + OFF_A_LO);
    }
    uint32_t bhi[4][2], blo[4][2];
#pragma unroll
    for (int np = 0; np < 2; np++) {
      const uint32_t bd = st + OFF_B + (kk + rsel) * B_STRIDE_B +
                          ((uint32_t)(ntr + np * 16) + osel * 8u) * 2u;
      uint32_t r4[4];
      ldmx4t(r4, bd);
      bhi[np * 2][0] = r4[0];
      bhi[np * 2][1] = r4[1];
      bhi[np * 2 + 1][0] = r4[2];
      bhi[np * 2 + 1][1] = r4[3];
      ldmx4t(r4, bd + OFF_B_LO);
      blo[np * 2][0] = r4[0];
      blo[np * 2][1] = r4[1];
      blo[np * 2 + 1][0] = r4[2];
      blo[np * 2 + 1][1] = r4[3];
    }
#pragma unroll
    for (int mi = 0; mi < 4; mi++)
#pragma unroll
      for (int ni = 0; ni < 4; ni++) {
        mma16816(acc[mi][ni], ahi[mi], bhi[ni]);
        mma16816(acc[mi][ni], alo[mi], bhi[ni]);
        mma16816(acc[mi][ni], ahi[mi], blo[ni]);
      }
  }
}

template <int MODE>
__global__ __launch_bounds__(256) void gemm_mma(const float* __restrict__ bias,
                                                float* __restrict__ out) {
  extern __shared__ char sm[];
  const uint32_t sb = smem_u32(sm);
  const int t = threadIdx.x;
  const int lane = t & 31, wid = t >> 5;
  const int m0 = blockIdx.y * 128, n0 = blockIdx.x * 128;
  const int mtr = (wid >> 2) * 64;
  const int ntr = (wid & 3) * 32;

  float acc[4][4][4];
#pragma unroll
  for (int a = 0; a < 4; a++)
#pragma unroll
    for (int b = 0; b < 4; b++)
#pragma unroll
      for (int c = 0; c < 4; c++) acc[a][b][c] = 0.f;

  g_load_stage<MODE>(sb, m0, n0, 0, t);
  cpa_commit();
  g_load_stage<MODE>(sb + STAGE_SZ, m0, n0, 32, t);
  cpa_commit();

#pragma unroll 1
  for (int c = 0; c < 32; c++) {
    if (c + 2 < 32) {
      g_load_stage<MODE>(sb + (uint32_t)((c + 2) % 3) * STAGE_SZ, m0, n0,
                         (c + 2) * 32, t);
      cpa_commit();
    }
    if (c < 30) {
      CP_WAIT(2);
    } else if (c == 30) {
      CP_WAIT(1);
    } else {
      CP_WAIT(0);
    }
    __syncthreads();
    g_compute_stage(sb + (uint32_t)(c % 3) * STAGE_SZ, acc, lane, mtr, ntr);
    __syncthreads();
  }

#pragma unroll
  for (int mi = 0; mi < 4; mi++) {
#pragma unroll
    for (int ni = 0; ni < 4; ni++) {
      const int r0 = mtr + mi * 16 + (lane >> 2);
      const int cc = ntr + ni * 8 + (lane & 3) * 2;
      const int n = n0 + cc;
      const float b0 = __ldg(&bias[n]);
      const float b1 = __ldg(&bias[n + 1]);
#pragma unroll
      for (int h = 0; h < 2; h++) {
        const int m = m0 + r0 + h * 8;
        float v0 = acc[mi][ni][h * 2 + 0] + b0;
        float v1 = acc[mi][ni][h * 2 + 1] + b1;
        if (MODE == 0) {
          const int bb = m >> 11, ss = m & 2047;
          const int which = n >> 10;
          const int hh = (n >> 6) & 15;
          const int dd = n & 63;
          unsigned short *dh, *dl;
          if (which == 0) {
            dh = g_q_hi; dl = g_q_lo;
            v0 *= 0.125f;  // fold 1/sqrt(hd) into q (exact)
            v1 *= 0.125f;
          } else if (which == 1) {
            dh = g_k_hi; dl = g_k_lo;
          } else {
            dh = g_v_hi; dl = g_v_lo;
          }
          const int idx = ((bb * NH + hh) * NS + ss) * NHD + dd;
          uint32_t hp, lp;
          cvt_pair(v0, v1, hp, lp);
          *(uint32_t*)(dh + idx) = hp;
          *(uint32_t*)(dl + idx) = lp;
        } else {
          *(float2*)&out[m * ND + n] = make_float2(v0, v1);
        }
      }
    }
  }
}

// ---------------------------------------------------------------------------
// Causal flash attention, bf16x3 mma.sync, cp.async double-buffered KV.
// Br=128 (8 warps x 16 q rows), Bc=64, hd=64. Row stride 144 B.
// Stage (36864 B): K_hi(9216) K_lo(9216) V_hi(9216) V_lo(9216).
// Q staged once into stage0 region, frags held in regs for whole loop.
// ---------------------------------------------------------------------------
#define FSTR 144u
#define FPL 9216u
#define FSTG 36864u
#define FLASH_SMEM (2 * 36864)

__device__ __forceinline__ void f_load_kv(uint32_t st, int bh, int k0, int t) {
  const unsigned short* pl[4] = {g_k_hi, g_k_lo, g_v_hi, g_v_lo};
#pragma unroll
  for (int i = 0; i < 8; i++) {
    const int idx = i * 256 + t;
    const int plane = idx >> 9, id = idx & 511;
    const int row = id >> 3, q = id & 7;
    cpa16(st + (uint32_t)plane * FPL + (uint32_t)row * FSTR + (uint32_t)q * 16u,
          pl[plane] + (bh * NS + k0 + row) * NHD + q * 8);
  }
}

__global__ __launch_bounds__(256) void flash_mma() {
  extern __shared__ char fsm[];
  const int bh = blockIdx.y;
  const int q0 = blockIdx.x * 128;
  const int t = threadIdx.x, lane = t & 31, wid = t >> 5;
  const uint32_t sbF = smem_u32(fsm);
  const uint32_t rsel = (uint32_t)(lane & 15), osel = (uint32_t)(lane >> 4);

  // Stage Q planes (hi at +0, lo at +18432) and extract fragments
  {
    const unsigned short* pl[2] = {g_q_hi, g_q_lo};
#pragma unroll
    for (int i = 0; i < 8; i++) {
      const int idx = i * 256 + t;
      const int plane = idx >> 10, id = idx & 1023;
      const int row = id >> 3, q = id & 7;
      cpa16(sbF + (uint32_t)plane * 18432u + (uint32_t)row * FSTR +
                (uint32_t)q * 16u,
            pl[plane] + (bh * NS + q0 + row) * NHD + q * 8);
    }
    cpa_commit();
    CP_WAIT(0);
    __syncthreads();
  }
  uint32_t qh[4][4], ql[4][4];
#pragma unroll
  for (int ks = 0; ks < 4; ks++) {
    const uint32_t off = ((uint32_t)(wid * 16) + rsel) * FSTR +
                         ((uint32_t)ks * 16 + osel * 8) * 2;
    ldmx4(qh[ks], sbF + off);
    ldmx4(ql[ks], sbF + 18432u + off);
  }
  __syncthreads();

  float oc[8][4];
#pragma unroll
  for (int i = 0; i < 8; i++)
#pragma unroll
    for (int j = 0; j < 4; j++) oc[i][j] = 0.f;
  float m2[2] = {-1e30f, -1e30f}, l2[2] = {0.f, 0.f};

  const int jmax = (q0 + 128) / 64;
  f_load_kv(sbF, bh, 0, t);
  cpa_commit();

  for (int jt = 0; jt < jmax; jt++) {
    const int k0 = jt * 64;
    if (jt + 1 < jmax) {
      f_load_kv(sbF + (uint32_t)((jt + 1) & 1) * FSTG, bh, (jt + 1) * 64, t);
      cpa_commit();
      CP_WAIT(1);
    } else {
      CP_WAIT(0);
    }
    __syncthreads();
    const uint32_t st = sbF + (uint32_t)(jt & 1) * FSTG;

    // S = Q K^T (K plane is [key][d] row-major -> non-trans ldmatrix)
    float sf[8][4];
#pragma unroll
    for (int i = 0; i < 8; i++)
#pragma unroll
      for (int j = 0; j < 4; j++) sf[i][j] = 0.f;

#pragma unroll
    for (int ks = 0; ks < 4; ks++) {
#pragma unroll
      for (int p = 0; p < 4; p++) {
        const uint32_t addr =
            st +
            ((uint32_t)(p * 16) + (uint32_t)(lane & 7) +
             (uint32_t)(lane >> 4) * 8) *
                FSTR +
            ((uint32_t)ks * 16 + (uint32_t)((lane >> 3) & 1) * 8) * 2;
        uint32_t kh[4], kl[4];
        ldmx4(kh, addr);
        ldmx4(kl, addr + FPL);
        mma16816(sf[2 * p], qh[ks], kh);
        mma16816(sf[2 * p], ql[ks], kh);
        mma16816(sf[2 * p], qh[ks], kl);
        mma16816(sf[2 * p + 1], qh[ks], kh + 2);
        mma16816(sf[2 * p + 1], ql[ks], kh + 2);
        mma16816(sf[2 * p + 1], qh[ks], kl + 2);
      }
    }

    // Causal mask
    const int r0g = q0 + wid * 16 + (lane >> 2);
    if (k0 + 63 > q0 + wid * 16) {
#pragma unroll
      for (int nt = 0; nt < 8; nt++) {
        const int c = k0 + nt * 8 + (lane & 3) * 2;
        if (c > r0g) sf[nt][0] = -1e30f;
        if (c + 1 > r0g) sf[nt][1] = -1e30f;
        if (c > r0g + 8) sf[nt][2] = -1e30f;
        if (c + 1 > r0g + 8) sf[nt][3] = -1e30f;
      }
    }

    // Online softmax (2 rows/thread; row lives in quad xor 1,2)
#pragma unroll
    for (int h = 0; h < 2; h++) {
      float mx = -1e30f;
#pragma unroll
      for (int nt = 0; nt < 8; nt++)
        mx = fmaxf(mx, fmaxf(sf[nt][2 * h], sf[nt][2 * h + 1]));
      mx = fmaxf(mx, __shfl_xor_sync(0xffffffffu, mx, 1));
      mx = fmaxf(mx, __shfl_xor_sync(0xffffffffu, mx, 2));
      const float mnew = fmaxf(m2[h], mx);
      const float alpha = __expf(m2[h] - mnew);
      m2[h] = mnew;
      float ps = 0.f;
#pragma unroll
      for (int nt = 0; nt < 8; nt++) {
        sf[nt][2 * h] = __expf(sf[nt][2 * h] - mnew);
        sf[nt][2 * h + 1] = __expf(sf[nt][2 * h + 1] - mnew);
        ps += sf[nt][2 * h] + sf[nt][2 * h + 1];
      }
      ps += __shfl_xor_sync(0xffffffffu, ps, 1);
      ps += __shfl_xor_sync(0xffffffffu, ps, 2);
      l2[h] = l2[h] * alpha + ps;
#pragma unroll
      for (int dt = 0; dt < 8; dt++) {
        oc[dt][2 * h] *= alpha;
        oc[dt][2 * h + 1] *= alpha;
      }
    }

    // Pack P into PV A-fragments (register-only)
    uint32_t ph[4][4], pl[4][4];
#pragma unroll
    for (int kk = 0; kk < 4; kk++) {
      cvt_pair(sf[2 * kk][0], sf[2 * kk][1], ph[kk][0], pl[kk][0]);
      cvt_pair(sf[2 * kk][2], sf[2 * kk][3], ph[kk][1], pl[kk][1]);
      cvt_pair(sf[2 * kk + 1][0], sf[2 * kk + 1][1], ph[kk][2], pl[kk][2]);
      cvt_pair(sf[2 * kk + 1][2], sf[2 * kk + 1][3], ph[kk][3], pl[kk][3]);
    }

    // O += P V (V plane is [key][d] -> trans ldmatrix)
#pragma unroll
    for (int kk = 0; kk < 4; kk++) {
#pragma unroll
      for (int dp = 0; dp < 4; dp++) {
        const uint32_t addr = st + 2 * FPL + ((uint32_t)kk * 16 + rsel) * FSTR +
                              ((uint32_t)(dp * 16) + osel * 8) * 2;
        uint32_t vh[4], vl[4];
        ldmx4t(vh, addr);
        ldmx4t(vl, addr + FPL);
        mma16816(oc[2 * dp], ph[kk], vh);
        mma16816(oc[2 * dp], pl[kk], vh);
        mma16816(oc[2 * dp], ph[kk], vl);
        mma16816(oc[2 * dp + 1], ph[kk], vh + 2);
        mma16816(oc[2 * dp + 1], pl[kk], vh + 2);
        mma16816(oc[2 * dp + 1], ph[kk], vl + 2);
      }
    }
    __syncthreads();
  }

  // Normalize, split to bf16 hi/lo planes for the out-proj GEMM
  const int r0g = q0 + wid * 16 + (lane >> 2);
#pragma unroll
  for (int h = 0; h < 2; h++) {
    const float inv = 1.f / l2[h];
    const int base = (bh * NS + r0g + h * 8) * NHD + (lane & 3) * 2;
#pragma unroll
    for (int dt = 0; dt < 8; dt++) {
      uint32_t hp, lp;
      cvt_pair(oc[dt][2 * h] * inv, oc[dt][2 * h + 1] * inv, hp, lp);
      *(uint32_t*)(g_attn_hi + base + dt * 8) = hp;
      *(uint32_t*)(g_attn_lo + base + dt * 8) = lp;
    }
  }
}

// ---------------------------------------------------------------------------
// Launch. Inputs: x, mask(ignored; causal hardcoded), Wqkv, bqkv, Wo, bo.
// ---------------------------------------------------------------------------
extern "C" void kernel_launch(void* const* d_in, const int* in_sizes, int n_in,
                              void* d_out, int out_size) {
  (void)in_sizes;
  (void)n_in;
  (void)out_size;
  const float* x = (const float*)d_in[0];
  const float* Wqkv = (const float*)d_in[2];
  const float* bqkv = (const float*)d_in[3];
  const float* Wo = (const float*)d_in[4];
  const float* bo = (const float*)d_in[5];
  float* out = (float*)d_out;

  static bool attr_set = false;
  if (!attr_set) {
    cudaFuncSetAttribute(gemm_mma<0>,
                         cudaFuncAttributeMaxDynamicSharedMemorySize,
                         GEMM_SMEM);
    cudaFuncSetAttribute(gemm_mma<1>,
                         cudaFuncAttributeMaxDynamicSharedMemorySize,
                         GEMM_SMEM);
    cudaFuncSetAttribute(flash_mma,
                         cudaFuncAttributeMaxDynamicSharedMemorySize,
                         FLASH_SMEM);
    attr_set = true;
  }

  unsigned short *xh, *xl, *qkh, *qkl, *woh, *wol;
  cudaGetSymbolAddress((void**)&xh, g_x_hi);
  cudaGetSymbolAddress((void**)&xl, g_x_lo);
  cudaGetSymbolAddress((void**)&qkh, g_wqkv_hi);
  cudaGetSymbolAddress((void**)&qkl, g_wqkv_lo);
  cudaGetSymbolAddress((void**)&woh, g_wo_hi);
  cudaGetSymbolAddress((void**)&wol, g_wo_lo);

  cvt_planes<<<4096, 256>>>(x, xh, xl);
  cvt_planes<<<3072, 256>>>(Wqkv, qkh, qkl);
  cvt_planes<<<1024, 256>>>(Wo, woh, wol);

  gemm_mma<0><<<dim3(3072 / 128, 4096 / 128), 256, GEMM_SMEM>>>(bqkv, nullptr);
  flash_mma<<<dim3(NS / 128, NB * NH), 256, FLASH_SMEM>>>();
  gemm_mma<1><<<dim3(ND / 128, 4096 / 128), 256, GEMM_SMEM>>>(bo, out);
}

// round 14
// speedup vs baseline: 2.9641x; 1.0961x over previous
#include <cuda_runtime.h>
#include <cuda_bf16.h>
#include <cstdint>

#define NB 2
#define NS 2048
#define ND 1024
#define NH 16
#define NHD 64
#define BHS (NB * NH * NS * NHD)

// Persistent bf16 hi/lo planes (allocation-free rule: __device__ globals)
__device__ unsigned short g_x_hi[4096 * ND], g_x_lo[4096 * ND];
__device__ unsigned short g_wqkv_hi[ND * 3072], g_wqkv_lo[ND * 3072];
__device__ unsigned short g_wo_hi[ND * ND], g_wo_lo[ND * ND];
__device__ unsigned short g_q_hi[BHS], g_q_lo[BHS];
__device__ unsigned short g_k_hi[BHS], g_k_lo[BHS];
__device__ unsigned short g_v_hi[BHS], g_v_lo[BHS];
__device__ unsigned short g_attn_hi[BHS], g_attn_lo[BHS];

// ---------------------------------------------------------------------------
// Helpers
// ---------------------------------------------------------------------------
__device__ __forceinline__ uint32_t smem_u32(const void* p) {
  uint32_t a;
  asm("{ .reg .u64 t; cvta.to.shared.u64 t, %1; cvt.u32.u64 %0, t; }"
      : "=r"(a) : "l"(p));
  return a;
}
__device__ __forceinline__ void ldmx4(uint32_t* r, uint32_t a) {
  asm volatile(
      "ldmatrix.sync.aligned.m8n8.x4.shared.b16 {%0,%1,%2,%3}, [%4];"
      : "=r"(r[0]), "=r"(r[1]), "=r"(r[2]), "=r"(r[3])
      : "r"(a));
}
__device__ __forceinline__ void ldmx4t(uint32_t* r, uint32_t a) {
  asm volatile(
      "ldmatrix.sync.aligned.m8n8.x4.trans.shared.b16 {%0,%1,%2,%3}, [%4];"
      : "=r"(r[0]), "=r"(r[1]), "=r"(r[2]), "=r"(r[3])
      : "r"(a));
}
__device__ __forceinline__ void mma16816(float* c, const uint32_t* a,
                                         const uint32_t* b) {
  asm volatile(
      "mma.sync.aligned.m16n8k16.row.col.f32.bf16.bf16.f32 "
      "{%0,%1,%2,%3}, {%4,%5,%6,%7}, {%8,%9}, {%0,%1,%2,%3};"
      : "+f"(c[0]), "+f"(c[1]), "+f"(c[2]), "+f"(c[3])
      : "r"(a[0]), "r"(a[1]), "r"(a[2]), "r"(a[3]), "r"(b[0]), "r"(b[1]));
}
__device__ __forceinline__ void cvt_pair(float a, float b, uint32_t& hi,
                                         uint32_t& lo) {
  const uint32_t ah = (uint32_t)__bfloat16_as_ushort(__float2bfloat16_rn(a));
  const uint32_t bh = (uint32_t)__bfloat16_as_ushort(__float2bfloat16_rn(b));
  hi = (bh << 16) | ah;
  const float ar = a - __uint_as_float(ah << 16);
  const float br = b - __uint_as_float(bh << 16);
  const uint32_t al = (uint32_t)__bfloat16_as_ushort(__float2bfloat16_rn(ar));
  const uint32_t bl = (uint32_t)__bfloat16_as_ushort(__float2bfloat16_rn(br));
  lo = (bl << 16) | al;
}
__device__ __forceinline__ void cpa16(uint32_t dst, const void* src) {
  asm volatile("cp.async.cg.shared.global [%0], [%1], 16;" ::"r"(dst),
               "l"(src));
}
__device__ __forceinline__ void cpa_commit() {
  asm volatile("cp.async.commit_group;");
}
#define CP_WAIT(N) asm volatile("cp.async.wait_group " #N ";")

// ---------------------------------------------------------------------------
// fp32 -> bf16 hi/lo plane converter
// ---------------------------------------------------------------------------
__global__ void cvt_planes(const float* __restrict__ src,
                           unsigned short* __restrict__ hi,
                           unsigned short* __restrict__ lo) {
  const int i = blockIdx.x * blockDim.x + threadIdx.x;
  const float4 v = ((const float4*)src)[i];
  uint32_t h0, l0, h1, l1;
  cvt_pair(v.x, v.y, h0, l0);
  cvt_pair(v.z, v.w, h1, l1);
  ((uint2*)hi)[i] = make_uint2(h0, h1);
  ((uint2*)lo)[i] = make_uint2(l0, l1);
}

// ---------------------------------------------------------------------------
// bf16x3 tensor-core GEMM, cp.async 2-stage pipeline, 2 CTAs/SM.
// MODE 0: C[4096,3072] = x @ Wqkv + bqkv -> split into q/k/v hi/lo planes
// MODE 1: C[4096,1024] = attn @ Wo + bo -> d_out (fp32)
// Stage: A_hi(10240) A_lo(10240) B_hi(8704) B_lo(8704) = 37888 B
// ---------------------------------------------------------------------------
#define A_STRIDE_B 80u
#define OFF_A_LO 10240u
#define OFF_B 20480u
#define B_STRIDE_B 272u
#define OFF_B_LO 8704u
#define STAGE_SZ 37888u
#define GEMM_SMEM (2 * 37888)

template <int MODE>
__device__ __forceinline__ void g_load_stage(uint32_t st, int m0, int n0,
                                             int k0, int t) {
  const int NW = (MODE == 0) ? 3072 : 1024;
  const unsigned short* ap[2];
  const unsigned short* wp[2];
  if (MODE == 0) {
    ap[0] = g_x_hi; ap[1] = g_x_lo;
    wp[0] = g_wqkv_hi; wp[1] = g_wqkv_lo;
  } else {
    ap[0] = g_attn_hi; ap[1] = g_attn_lo;
    wp[0] = g_wo_hi; wp[1] = g_wo_lo;
  }
#pragma unroll
  for (int i = 0; i < 4; i++) {
    const int idx = i * 256 + t;
    const int plane = idx >> 9, id = idx & 511;
    const int r = id >> 2, q = id & 3;
    const unsigned short* src;
    if (MODE == 0) {
      src = ap[plane] + (m0 + r) * ND + k0 + q * 8;
    } else {
      const int m = m0 + r;
      const int bb = m >> 11, ss = m & 2047;
      const int k = k0 + q * 8;
      src = ap[plane] + bb * (NH * NS * NHD) + (k >> 6) * (NS * NHD) +
            ss * NHD + (k & 63);
    }
    cpa16(st + (uint32_t)plane * OFF_A_LO + (uint32_t)r * A_STRIDE_B +
              (uint32_t)q * 16u,
          src);
  }
#pragma unroll
  for (int i = 0; i < 4; i++) {
    const int idx = i * 256 + t;
    const int plane = idx >> 9, id = idx & 511;
    const int kr = id >> 4, nq = id & 15;
    cpa16(st + OFF_B + (uint32_t)plane * OFF_B_LO + (uint32_t)kr * B_STRIDE_B +
              (uint32_t)nq * 16u,
          wp[plane] + (k0 + kr) * NW + n0 + nq * 8);
  }
}

__device__ __forceinline__ void g_compute_stage(uint32_t st, float acc[4][4][4],
                                                int lane, int mtr, int ntr) {
  const uint32_t rsel = (uint32_t)(lane & 15);
  const uint32_t osel = (uint32_t)(lane >> 4);
#pragma unroll
  for (int ks = 0; ks < 2; ks++) {
    const uint32_t kk = (uint32_t)ks * 16u;
    uint32_t ahi[4][4], alo[4][4];
#pragma unroll
    for (int mi = 0; mi < 4; mi++) {
      const uint32_t ad = st + ((uint32_t)(mtr + mi * 16) + rsel) * A_STRIDE_B +
                          (kk + osel * 8u) * 2u;
      ldmx4(ahi[mi], ad);
      ldmx4(alo[mi], ad + OFF_A_LO);
    }
    uint32_t bhi[4][2], blo[4][2];
#pragma unroll
    for (int np = 0; np < 2; np++) {
      const uint32_t bd = st + OFF_B + (kk + rsel) * B_STRIDE_B +
                          ((uint32_t)(ntr + np * 16) + osel * 8u) * 2u;
      uint32_t r4[4];
      ldmx4t(r4, bd);
      bhi[np * 2][0] = r4[0];
      bhi[np * 2][1] = r4[1];
      bhi[np * 2 + 1][0] = r4[2];
      bhi[np * 2 + 1][1] = r4[3];
      ldmx4t(r4, bd + OFF_B_LO);
      blo[np * 2][0] = r4[0];
      blo[np * 2][1] = r4[1];
      blo[np * 2 + 1][0] = r4[2];
      blo[np * 2 + 1][1] = r4[3];
    }
#pragma unroll
    for (int mi = 0; mi < 4; mi++)
#pragma unroll
      for (int ni = 0; ni < 4; ni++) {
        mma16816(acc[mi][ni], ahi[mi], bhi[ni]);
        mma16816(acc[mi][ni], alo[mi], bhi[ni]);
        mma16816(acc[mi][ni], ahi[mi], blo[ni]);
      }
  }
}

template <int MODE>
__global__ __launch_bounds__(256, 2) void gemm_mma(
    const float* __restrict__ bias, float* __restrict__ out) {
  extern __shared__ char sm[];
  const uint32_t sb = smem_u32(sm);
  const int t = threadIdx.x;
  const int lane = t & 31, wid = t >> 5;
  const int m0 = blockIdx.y * 128, n0 = blockIdx.x * 128;
  const int mtr = (wid >> 2) * 64;
  const int ntr = (wid & 3) * 32;

  float acc[4][4][4];
#pragma unroll
  for (int a = 0; a < 4; a++)
#pragma unroll
    for (int b = 0; b < 4; b++)
#pragma unroll
      for (int c = 0; c < 4; c++) acc[a][b][c] = 0.f;

  g_load_stage<MODE>(sb, m0, n0, 0, t);
  cpa_commit();

#pragma unroll 1
  for (int c = 0; c < 32; c++) {
    if (c + 1 < 32) {
      g_load_stage<MODE>(sb + (uint32_t)((c + 1) & 1) * STAGE_SZ, m0, n0,
                         (c + 1) * 32, t);
      cpa_commit();
      CP_WAIT(1);
    } else {
      CP_WAIT(0);
    }
    __syncthreads();
    g_compute_stage(sb + (uint32_t)(c & 1) * STAGE_SZ, acc, lane, mtr, ntr);
    __syncthreads();
  }

#pragma unroll
  for (int mi = 0; mi < 4; mi++) {
#pragma unroll
    for (int ni = 0; ni < 4; ni++) {
      const int r0 = mtr + mi * 16 + (lane >> 2);
      const int cc = ntr + ni * 8 + (lane & 3) * 2;
      const int n = n0 + cc;
      const float b0 = __ldg(&bias[n]);
      const float b1 = __ldg(&bias[n + 1]);
#pragma unroll
      for (int h = 0; h < 2; h++) {
        const int m = m0 + r0 + h * 8;
        float v0 = acc[mi][ni][h * 2 + 0] + b0;
        float v1 = acc[mi][ni][h * 2 + 1] + b1;
        if (MODE == 0) {
          const int bb = m >> 11, ss = m & 2047;
          const int which = n >> 10;
          const int hh = (n >> 6) & 15;
          const int dd = n & 63;
          unsigned short *dh, *dl;
          if (which == 0) {
            dh = g_q_hi; dl = g_q_lo;
            v0 *= 0.125f;  // fold 1/sqrt(hd) into q (exact)
            v1 *= 0.125f;
          } else if (which == 1) {
            dh = g_k_hi; dl = g_k_lo;
          } else {
            dh = g_v_hi; dl = g_v_lo;
          }
          const int idx = ((bb * NH + hh) * NS + ss) * NHD + dd;
          uint32_t hp, lp;
          cvt_pair(v0, v1, hp, lp);
          *(uint32_t*)(dh + idx) = hp;
          *(uint32_t*)(dl + idx) = lp;
        } else {
          *(float2*)&out[m * ND + n] = make_float2(v0, v1);
        }
      }
    }
  }
}

// ---------------------------------------------------------------------------
// Causal flash attention, bf16x3 mma.sync, cp.async double-buffered KV
// (unchanged from R11, passing).
// ---------------------------------------------------------------------------
#define FSTR 144u
#define FPL 9216u
#define FSTG 36864u
#define FLASH_SMEM (2 * 36864)

__device__ __forceinline__ void f_load_kv(uint32_t st, int bh, int k0, int t) {
  const unsigned short* pl[4] = {g_k_hi, g_k_lo, g_v_hi, g_v_lo};
#pragma unroll
  for (int i = 0; i < 8; i++) {
    const int idx = i * 256 + t;
    const int plane = idx >> 9, id = idx & 511;
    const int row = id >> 3, q = id & 7;
    cpa16(st + (uint32_t)plane * FPL + (uint32_t)row * FSTR + (uint32_t)q * 16u,
          pl[plane] + (bh * NS + k0 + row) * NHD + q * 8);
  }
}

__global__ __launch_bounds__(256) void flash_mma() {
  extern __shared__ char fsm[];
  const int bh = blockIdx.y;
  const int q0 = blockIdx.x * 128;
  const int t = threadIdx.x, lane = t & 31, wid = t >> 5;
  const uint32_t sbF = smem_u32(fsm);
  const uint32_t rsel = (uint32_t)(lane & 15), osel = (uint32_t)(lane >> 4);

  // Stage Q planes (hi at +0, lo at +18432) and extract fragments
  {
    const unsigned short* pl[2] = {g_q_hi, g_q_lo};
#pragma unroll
    for (int i = 0; i < 8; i++) {
      const int idx = i * 256 + t;
      const int plane = idx >> 10, id = idx & 1023;
      const int row = id >> 3, q = id & 7;
      cpa16(sbF + (uint32_t)plane * 18432u + (uint32_t)row * FSTR +
                (uint32_t)q * 16u,
            pl[plane] + (bh * NS + q0 + row) * NHD + q * 8);
    }
    cpa_commit();
    CP_WAIT(0);
    __syncthreads();
  }
  uint32_t qh[4][4], ql[4][4];
#pragma unroll
  for (int ks = 0; ks < 4; ks++) {
    const uint32_t off = ((uint32_t)(wid * 16) + rsel) * FSTR +
                         ((uint32_t)ks * 16 + osel * 8) * 2;
    ldmx4(qh[ks], sbF + off);
    ldmx4(ql[ks], sbF + 18432u + off);
  }
  __syncthreads();

  float oc[8][4];
#pragma unroll
  for (int i = 0; i < 8; i++)
#pragma unroll
    for (int j = 0; j < 4; j++) oc[i][j] = 0.f;
  float m2[2] = {-1e30f, -1e30f}, l2[2] = {0.f, 0.f};

  const int jmax = (q0 + 128) / 64;
  f_load_kv(sbF, bh, 0, t);
  cpa_commit();

  for (int jt = 0; jt < jmax; jt++) {
    const int k0 = jt * 64;
    if (jt + 1 < jmax) {
      f_load_kv(sbF + (uint32_t)((jt + 1) & 1) * FSTG, bh, (jt + 1) * 64, t);
      cpa_commit();
      CP_WAIT(1);
    } else {
      CP_WAIT(0);
    }
    __syncthreads();
    const uint32_t st = sbF + (uint32_t)(jt & 1) * FSTG;

    // S = Q K^T (K plane is [key][d] row-major -> non-trans ldmatrix)
    float sf[8][4];
#pragma unroll
    for (int i = 0; i < 8; i++)
#pragma unroll
      for (int j = 0; j < 4; j++) sf[i][j] = 0.f;

#pragma unroll
    for (int ks = 0; ks < 4; ks++) {
#pragma unroll
      for (int p = 0; p < 4; p++) {
        const uint32_t addr =
            st +
            ((uint32_t)(p * 16) + (uint32_t)(lane & 7) +
             (uint32_t)(lane >> 4) * 8) *
                FSTR +
            ((uint32_t)ks * 16 + (uint32_t)((lane >> 3) & 1) * 8) * 2;
        uint32_t kh[4], kl[4];
        ldmx4(kh, addr);
        ldmx4(kl, addr + FPL);
        mma16816(sf[2 * p], qh[ks], kh);
        mma16816(sf[2 * p], ql[ks], kh);
        mma16816(sf[2 * p], qh[ks], kl);
        mma16816(sf[2 * p + 1], qh[ks], kh + 2);
        mma16816(sf[2 * p + 1], ql[ks], kh + 2);
        mma16816(sf[2 * p + 1], qh[ks], kl + 2);
      }
    }

    // Causal mask
    const int r0g = q0 + wid * 16 + (lane >> 2);
    if (k0 + 63 > q0 + wid * 16) {
#pragma unroll
      for (int nt = 0; nt < 8; nt++) {
        const int c = k0 + nt * 8 + (lane & 3) * 2;
        if (c > r0g) sf[nt][0] = -1e30f;
        if (c + 1 > r0g) sf[nt][1] = -1e30f;
        if (c > r0g + 8) sf[nt][2] = -1e30f;
        if (c + 1 > r0g + 8) sf[nt][3] = -1e30f;
      }
    }

    // Online softmax (2 rows/thread; row lives in quad xor 1,2)
#pragma unroll
    for (int h = 0; h < 2; h++) {
      float mx = -1e30f;
#pragma unroll
      for (int nt = 0; nt < 8; nt++)
        mx = fmaxf(mx, fmaxf(sf[nt][2 * h], sf[nt][2 * h + 1]));
      mx = fmaxf(mx, __shfl_xor_sync(0xffffffffu, mx, 1));
      mx = fmaxf(mx, __shfl_xor_sync(0xffffffffu, mx, 2));
      const float mnew = fmaxf(m2[h], mx);
      const float alpha = __expf(m2[h] - mnew);
      m2[h] = mnew;
      float ps = 0.f;
#pragma unroll
      for (int nt = 0; nt < 8; nt++) {
        sf[nt][2 * h] = __expf(sf[nt][2 * h] - mnew);
        sf[nt][2 * h + 1] = __expf(sf[nt][2 * h + 1] - mnew);
        ps += sf[nt][2 * h] + sf[nt][2 * h + 1];
      }
      ps += __shfl_xor_sync(0xffffffffu, ps, 1);
      ps += __shfl_xor_sync(0xffffffffu, ps, 2);
      l2[h] = l2[h] * alpha + ps;
#pragma unroll
      for (int dt = 0; dt < 8; dt++) {
        oc[dt][2 * h] *= alpha;
        oc[dt][2 * h + 1] *= alpha;
      }
    }

    // Pack P into PV A-fragments (register-only)
    uint32_t ph[4][4], pl[4][4];
#pragma unroll
    for (int kk = 0; kk < 4; kk++) {
      cvt_pair(sf[2 * kk][0], sf[2 * kk][1], ph[kk][0], pl[kk][0]);
      cvt_pair(sf[2 * kk][2], sf[2 * kk][3], ph[kk][1], pl[kk][1]);
      cvt_pair(sf[2 * kk + 1][0], sf[2 * kk + 1][1], ph[kk][2], pl[kk][2]);
      cvt_pair(sf[2 * kk + 1][2], sf[2 * kk + 1][3], ph[kk][3], pl[kk][3]);
    }

    // O += P V (V plane is [key][d] -> trans ldmatrix)
#pragma unroll
    for (int kk = 0; kk < 4; kk++) {
#pragma unroll
      for (int dp = 0; dp < 4; dp++) {
        const uint32_t addr = st + 2 * FPL + ((uint32_t)kk * 16 + rsel) * FSTR +
                              ((uint32_t)(dp * 16) + osel * 8) * 2;
        uint32_t vh[4], vl[4];
        ldmx4t(vh, addr);
        ldmx4t(vl, addr + FPL);
        mma16816(oc[2 * dp], ph[kk], vh);
        mma16816(oc[2 * dp], pl[kk], vh);
        mma16816(oc[2 * dp], ph[kk], vl);
        mma16816(oc[2 * dp + 1], ph[kk], vh + 2);
        mma16816(oc[2 * dp + 1], pl[kk], vh + 2);
        mma16816(oc[2 * dp + 1], ph[kk], vl + 2);
      }
    }
    __syncthreads();
  }

  // Normalize, split to bf16 hi/lo planes for the out-proj GEMM
  const int r0g = q0 + wid * 16 + (lane >> 2);
#pragma unroll
  for (int h = 0; h < 2; h++) {
    const float inv = 1.f / l2[h];
    const int base = (bh * NS + r0g + h * 8) * NHD + (lane & 3) * 2;
#pragma unroll
    for (int dt = 0; dt < 8; dt++) {
      uint32_t hp, lp;
      cvt_pair(oc[dt][2 * h] * inv, oc[dt][2 * h + 1] * inv, hp, lp);
      *(uint32_t*)(g_attn_hi + base + dt * 8) = hp;
      *(uint32_t*)(g_attn_lo + base + dt * 8) = lp;
    }
  }
}

// ---------------------------------------------------------------------------
// Launch. Inputs: x, mask(ignored; causal hardcoded), Wqkv, bqkv, Wo, bo.
// ---------------------------------------------------------------------------
extern "C" void kernel_launch(void* const* d_in, const int* in_sizes, int n_in,
                              void* d_out, int out_size) {
  (void)in_sizes;
  (void)n_in;
  (void)out_size;
  const float* x = (const float*)d_in[0];
  const float* Wqkv = (const float*)d_in[2];
  const float* bqkv = (const float*)d_in[3];
  const float* Wo = (const float*)d_in[4];
  const float* bo = (const float*)d_in[5];
  float* out = (float*)d_out;

  static bool attr_set = false;
  if (!attr_set) {
    cudaFuncSetAttribute(gemm_mma<0>,
                         cudaFuncAttributeMaxDynamicSharedMemorySize,
                         GEMM_SMEM);
    cudaFuncSetAttribute(gemm_mma<1>,
                         cudaFuncAttributeMaxDynamicSharedMemorySize,
                         GEMM_SMEM);
    cudaFuncSetAttribute(flash_mma,
                         cudaFuncAttributeMaxDynamicSharedMemorySize,
                         FLASH_SMEM);
    attr_set = true;
  }

  unsigned short *xh, *xl, *qkh, *qkl, *woh, *wol;
  cudaGetSymbolAddress((void**)&xh, g_x_hi);
  cudaGetSymbolAddress((void**)&xl, g_x_lo);
  cudaGetSymbolAddress((void**)&qkh, g_wqkv_hi);
  cudaGetSymbolAddress((void**)&qkl, g_wqkv_lo);
  cudaGetSymbolAddress((void**)&woh, g_wo_hi);
  cudaGetSymbolAddress((void**)&wol, g_wo_lo);

  cvt_planes<<<4096, 256>>>(x, xh, xl);
  cvt_planes<<<3072, 256>>>(Wqkv, qkh, qkl);
  cvt_planes<<<1024, 256>>>(Wo, woh, wol);

  gemm_mma<0><<<dim3(3072 / 128, 4096 / 128), 256, GEMM_SMEM>>>(bqkv, nullptr);
  flash_mma<<<dim3(NS / 128, NB * NH), 256, FLASH_SMEM>>>();
  gemm_mma<1><<<dim3(ND / 128, 4096 / 128), 256, GEMM_SMEM>>>(bo, out);
}